// round 1
// baseline (speedup 1.0000x reference)
#include <cuda_runtime.h>
#include <math.h>

#define N_NODES 200000
#define N_EDGES 500000
#define DIM 128
#define KQV_COLS 768   // [k0 q0 v0 | k1 q1 v1]

// ---------------- scratch (device globals; no allocation allowed) ----------------
__device__ __align__(16) float g_WC[128 * KQV_COLS];           // fused weights [i][c]
__device__ __align__(16) float g_bc[KQV_COLS];                 // fused bias
__device__ __align__(16) float g_KQV[(size_t)N_NODES * KQV_COLS]; // 614 MB
__device__ __align__(16) float g_upd[(size_t)N_NODES * DIM];      // 102 MB
__device__ __align__(16) float g_s[2 * N_NODES * 2];              // per-rel segment sums [N,H]
__device__ __align__(16) float g_att[2 * (size_t)N_EDGES * 2];    // per-rel exp(logit) [E,H]

// ---------------- zero scratch that is accumulated into ----------------
__global__ void zero_kernel() {
    size_t i0 = blockIdx.x * (size_t)blockDim.x + threadIdx.x;
    size_t stride = gridDim.x * (size_t)blockDim.x;
    float4* u = (float4*)g_upd;
    const size_t nu = (size_t)N_NODES * DIM / 4;
    for (size_t i = i0; i < nu; i += stride) u[i] = make_float4(0.f, 0.f, 0.f, 0.f);
    float4* s = (float4*)g_s;
    const size_t ns = (size_t)2 * N_NODES * 2 / 4;
    for (size_t i = i0; i < ns; i += stride) s[i] = make_float4(0.f, 0.f, 0.f, 0.f);
}

// ---------------- fold node-type and edge-type linears into one weight ----------------
// col c = r*384 + t*128 + j  (t: 0=k, 1=q(*SCALE), 2=v)
// WC[i][c] = sum_m Wt[i][m] * We_r[m][j] * scale
// bc[c]    = (sum_m bt[m] * We_r[m][j] + be_r[j]) * scale
__global__ void prep_kernel(const float* __restrict__ Wk, const float* __restrict__ bk,
                            const float* __restrict__ Wq, const float* __restrict__ bq,
                            const float* __restrict__ Wv, const float* __restrict__ bv,
                            const float* __restrict__ We0, const float* __restrict__ be0,
                            const float* __restrict__ We1, const float* __restrict__ be1) {
    int c = blockIdx.x;           // 0..767
    int i = threadIdx.x;          // 0..127
    int r = c / 384;
    int rem = c % 384;
    int t = rem / 128;
    int j = rem % 128;
    const float* We = r ? We1 : We0;
    const float* be = r ? be1 : be0;
    const float* Wt = (t == 0) ? Wk : (t == 1) ? Wq : Wv;
    const float* bt = (t == 0) ? bk : (t == 1) ? bq : bv;
    const float scale = (t == 1) ? 0.125f : 1.0f;   // SCALE = 64^-0.5

    __shared__ float sWe[128];
    sWe[i] = We[i * 128 + j];
    __syncthreads();

    float acc = 0.f;
#pragma unroll 8
    for (int m = 0; m < 128; m++) acc += Wt[i * 128 + m] * sWe[m];
    g_WC[i * KQV_COLS + c] = acc * scale;

    if (i == 0) {
        float b = 0.f;
        for (int m = 0; m < 128; m++) b += bt[m] * sWe[m];
        g_bc[c] = (b + be[j]) * scale;
    }
}

// ---------------- fp32 tiled GEMM: C[M][COLS] = A[M][128] * W[128][COLS] + bias ----------------
// Tile: 64x64, BK=64 (x2), 256 threads, 4x4 per-thread microtile.
__global__ void __launch_bounds__(256) sgemm_kernel(const float* __restrict__ A,
                                                    const float* __restrict__ W,
                                                    const float* __restrict__ bias,
                                                    float* __restrict__ C, int COLS) {
    __shared__ float sA[64][64];   // [k][m]
    __shared__ float sB[64][64];   // [k][n]
    const int m0 = blockIdx.y * 64;
    const int n0 = blockIdx.x * 64;
    const int tid = threadIdx.x;
    const int tm = (tid >> 4) * 4;
    const int tn = (tid & 15) * 4;

    float acc[4][4] = {};

    for (int kt = 0; kt < 2; kt++) {
        // load A tile (transpose into [k][m])
#pragma unroll
        for (int it = 0; it < 4; it++) {
            int idx = tid + it * 256;       // 0..1023
            int row = idx >> 4;             // 0..63
            int k4 = idx & 15;              // float4 within 64 k
            float4 va = *(const float4*)(A + (size_t)(m0 + row) * 128 + kt * 64 + k4 * 4);
            sA[k4 * 4 + 0][row] = va.x;
            sA[k4 * 4 + 1][row] = va.y;
            sA[k4 * 4 + 2][row] = va.z;
            sA[k4 * 4 + 3][row] = va.w;
        }
        // load W tile (already [k][n])
#pragma unroll
        for (int it = 0; it < 4; it++) {
            int idx = tid + it * 256;
            int k = idx >> 4;
            int n4 = idx & 15;
            *(float4*)&sB[k][n4 * 4] =
                *(const float4*)(W + (size_t)(kt * 64 + k) * COLS + n0 + n4 * 4);
        }
        __syncthreads();

#pragma unroll 8
        for (int k = 0; k < 64; k++) {
            float4 av = *(const float4*)&sA[k][tm];
            float4 bv = *(const float4*)&sB[k][tn];
            acc[0][0] += av.x * bv.x; acc[0][1] += av.x * bv.y; acc[0][2] += av.x * bv.z; acc[0][3] += av.x * bv.w;
            acc[1][0] += av.y * bv.x; acc[1][1] += av.y * bv.y; acc[1][2] += av.y * bv.z; acc[1][3] += av.y * bv.w;
            acc[2][0] += av.z * bv.x; acc[2][1] += av.z * bv.y; acc[2][2] += av.z * bv.z; acc[2][3] += av.z * bv.w;
            acc[3][0] += av.w * bv.x; acc[3][1] += av.w * bv.y; acc[3][2] += av.w * bv.z; acc[3][3] += av.w * bv.w;
        }
        __syncthreads();
    }

    float4 bb = *(const float4*)(bias + n0 + tn);
#pragma unroll
    for (int i = 0; i < 4; i++) {
        float4 o;
        o.x = acc[i][0] + bb.x;
        o.y = acc[i][1] + bb.y;
        o.z = acc[i][2] + bb.z;
        o.w = acc[i][3] + bb.w;
        *(float4*)(C + (size_t)(m0 + tm + i) * COLS + n0 + tn) = o;
    }
}

// ---------------- edge pass A: e = exp(k[src].q[dst]) per head; s[dst] += e ----------------
// One warp per edge. Softmax max-shift dropped (shift-invariant; logits are O(0.1)).
__global__ void __launch_bounds__(256) edge_a_kernel(const int* __restrict__ src,
                                                     const int* __restrict__ dst, int rel) {
    int warp = (blockIdx.x * blockDim.x + threadIdx.x) >> 5;
    int lane = threadIdx.x & 31;
    if (warp >= N_EDGES) return;
    int sn = src[warp];
    int dn = dst[warp];
    const int rbase = rel * 384;
    const float4* kr = (const float4*)(g_KQV + (size_t)sn * KQV_COLS + rbase);
    const float4* qr = (const float4*)(g_KQV + (size_t)dn * KQV_COLS + rbase + 128);
    float4 a = kr[lane];
    float4 b = qr[lane];
    float p = a.x * b.x + a.y * b.y + a.z * b.z + a.w * b.w;
    // reduce within each 16-lane half (head 0 = lanes 0-15, head 1 = lanes 16-31)
    p += __shfl_xor_sync(0xffffffffu, p, 1);
    p += __shfl_xor_sync(0xffffffffu, p, 2);
    p += __shfl_xor_sync(0xffffffffu, p, 4);
    p += __shfl_xor_sync(0xffffffffu, p, 8);
    float el = expf(p);
    float* s = g_s + rel * (N_NODES * 2);
    float* att = g_att + (size_t)rel * N_EDGES * 2;
    if (lane == 0) {
        att[(size_t)warp * 2 + 0] = el;
        atomicAdd(&s[dn * 2 + 0], el);
    }
    if (lane == 16) {
        att[(size_t)warp * 2 + 1] = el;
        atomicAdd(&s[dn * 2 + 1], el);
    }
}

// ---------------- edge pass B: upd[dst] += v[src] * (e / s[dst]) ----------------
__global__ void __launch_bounds__(256) edge_b_kernel(const int* __restrict__ src,
                                                     const int* __restrict__ dst, int rel) {
    int warp = (blockIdx.x * blockDim.x + threadIdx.x) >> 5;
    int lane = threadIdx.x & 31;
    if (warp >= N_EDGES) return;
    int sn = src[warp];
    int dn = dst[warp];
    const float* s = g_s + rel * (N_NODES * 2);
    const float* att = g_att + (size_t)rel * N_EDGES * 2;
    float w0 = att[(size_t)warp * 2 + 0] / s[dn * 2 + 0];
    float w1 = att[(size_t)warp * 2 + 1] / s[dn * 2 + 1];
    float w = (lane < 16) ? w0 : w1;
    const float4* vr = (const float4*)(g_KQV + (size_t)sn * KQV_COLS + rel * 384 + 256);
    float4 v = vr[lane];
    float* o = g_upd + (size_t)dn * DIM + lane * 4;
    atomicAdd(o + 0, v.x * w);
    atomicAdd(o + 1, v.y * w);
    atomicAdd(o + 2, v.z * w);
    atomicAdd(o + 3, v.w * w);
}

// ---------------- launch ----------------
extern "C" void kernel_launch(void* const* d_in, const int* in_sizes, int n_in,
                              void* d_out, int out_size) {
    const float* feat = (const float*)d_in[0];
    const int* src0 = (const int*)d_in[1];
    const int* dst0 = (const int*)d_in[2];
    const int* src1 = (const int*)d_in[3];
    const int* dst1 = (const int*)d_in[4];
    const float* Wk = (const float*)d_in[5];
    const float* bk = (const float*)d_in[6];
    const float* Wq = (const float*)d_in[7];
    const float* bq = (const float*)d_in[8];
    const float* Wv = (const float*)d_in[9];
    const float* bv = (const float*)d_in[10];
    const float* Wo = (const float*)d_in[11];
    const float* bo = (const float*)d_in[12];
    const float* We0 = (const float*)d_in[13];
    const float* be0 = (const float*)d_in[14];
    const float* We1 = (const float*)d_in[15];
    const float* be1 = (const float*)d_in[16];
    float* out = (float*)d_out;

    void *pWC, *pbc, *pKQV, *pupd;
    cudaGetSymbolAddress(&pWC, g_WC);
    cudaGetSymbolAddress(&pbc, g_bc);
    cudaGetSymbolAddress(&pKQV, g_KQV);
    cudaGetSymbolAddress(&pupd, g_upd);

    zero_kernel<<<2048, 256>>>();
    prep_kernel<<<KQV_COLS, 128>>>(Wk, bk, Wq, bq, Wv, bv, We0, be0, We1, be1);

    // KQV = feat @ WC + bc   ([200000,128] x [128,768])
    sgemm_kernel<<<dim3(KQV_COLS / 64, N_NODES / 64), 256>>>(
        feat, (const float*)pWC, (const float*)pbc, (float*)pKQV, KQV_COLS);

    const int eblocks = N_EDGES / 8;   // 8 warps per 256-thread block
    edge_a_kernel<<<eblocks, 256>>>(src0, dst0, 0);
    edge_a_kernel<<<eblocks, 256>>>(src1, dst1, 1);
    edge_b_kernel<<<eblocks, 256>>>(src0, dst0, 0);
    edge_b_kernel<<<eblocks, 256>>>(src1, dst1, 1);

    // out = upd @ Wo + bo    ([200000,128] x [128,128])
    sgemm_kernel<<<dim3(DIM / 64, N_NODES / 64), 256>>>(
        (const float*)pupd, Wo, bo, out, DIM);
}

// round 3
// speedup vs baseline: 2.1389x; 2.1389x over previous
#include <cuda_runtime.h>
#include <cuda_bf16.h>
#include <stdint.h>
#include <math.h>

#define N_NODES 200000
#define N_EDGES 500000
#define DIM 128
#define KQV_COLS 768   // [k0 q0 v0 | k1 q1 v1]

// ---------------- scratch (device globals; no allocation allowed) ----------------
__device__ __align__(16) float g_bc[KQV_COLS];                       // fused bias
__device__ __align__(16) __nv_bfloat16 g_WCt_hi[KQV_COLS * 128];     // fused W^T [n][k]
__device__ __align__(16) __nv_bfloat16 g_WCt_lo[KQV_COLS * 128];
__device__ __align__(16) __nv_bfloat16 g_Wot_hi[128 * 128];          // Wo^T [n][k]
__device__ __align__(16) __nv_bfloat16 g_Wot_lo[128 * 128];
__device__ __align__(16) float g_KQV[(size_t)N_NODES * KQV_COLS];    // 614 MB
__device__ __align__(16) float g_upd[(size_t)N_NODES * DIM];         // 102 MB
__device__ __align__(16) float g_s[2 * N_NODES * 2];                 // per-rel segment sums
__device__ __align__(16) float g_att[2 * (size_t)N_EDGES * 2];       // per-rel exp(logit)

// ---------------- helpers ----------------
static __device__ __forceinline__ uint32_t smem_u32(const void* p) {
    uint32_t a;
    asm("{ .reg .u64 t; cvta.to.shared.u64 t, %1; cvt.u32.u64 %0, t; }" : "=r"(a) : "l"(p));
    return a;
}
static __device__ __forceinline__ uint32_t pack2(__nv_bfloat16 a, __nv_bfloat16 b) {
    uint16_t ua = *(uint16_t*)&a, ub = *(uint16_t*)&b;
    return (uint32_t)ua | ((uint32_t)ub << 16);
}
static __device__ __forceinline__ void split2(float a, float b, uint32_t& h, uint32_t& l) {
    __nv_bfloat16 ha = __float2bfloat16_rn(a), hb = __float2bfloat16_rn(b);
    float ra = a - __bfloat162float(ha), rb = b - __bfloat162float(hb);
    h = pack2(ha, hb);
    l = pack2(__float2bfloat16_rn(ra), __float2bfloat16_rn(rb));
}

#define LDSM4(r, addr)                                                           \
    asm volatile("ldmatrix.sync.aligned.m8n8.x4.shared.b16 {%0,%1,%2,%3}, [%4];" \
                 : "=r"((r)[0]), "=r"((r)[1]), "=r"((r)[2]), "=r"((r)[3])        \
                 : "r"(addr))

#define MMA(c, a, b0, b1)                                                     \
    asm volatile(                                                             \
        "mma.sync.aligned.m16n8k16.row.col.f32.bf16.bf16.f32 "                \
        "{%0,%1,%2,%3},{%4,%5,%6,%7},{%8,%9},{%0,%1,%2,%3};"                  \
        : "+f"((c)[0]), "+f"((c)[1]), "+f"((c)[2]), "+f"((c)[3])              \
        : "r"((a)[0]), "r"((a)[1]), "r"((a)[2]), "r"((a)[3]), "r"(b0), "r"(b1))

#define CP_ASYNC16(dst, src) \
    asm volatile("cp.async.ca.shared.global [%0], [%1], 16;" :: "r"(dst), "l"(src))
#define CP_COMMIT() asm volatile("cp.async.commit_group;")
#define CP_WAIT(n) asm volatile("cp.async.wait_group %0;" :: "n"(n))

// ---------------- zero scratch that is accumulated into ----------------
__global__ void zero_kernel() {
    size_t i0 = blockIdx.x * (size_t)blockDim.x + threadIdx.x;
    size_t stride = gridDim.x * (size_t)blockDim.x;
    float4* u = (float4*)g_upd;
    const size_t nu = (size_t)N_NODES * DIM / 4;
    for (size_t i = i0; i < nu; i += stride) u[i] = make_float4(0.f, 0.f, 0.f, 0.f);
    float4* s = (float4*)g_s;
    const size_t ns = (size_t)2 * N_NODES * 2 / 4;
    for (size_t i = i0; i < ns; i += stride) s[i] = make_float4(0.f, 0.f, 0.f, 0.f);
}

// ---------------- fold node-type + edge-type linears; emit bf16 hi/lo transposed ----------------
__global__ void prep_kernel(const float* __restrict__ Wk, const float* __restrict__ bk,
                            const float* __restrict__ Wq, const float* __restrict__ bq,
                            const float* __restrict__ Wv, const float* __restrict__ bv,
                            const float* __restrict__ We0, const float* __restrict__ be0,
                            const float* __restrict__ We1, const float* __restrict__ be1) {
    int c = blockIdx.x;           // 0..767
    int i = threadIdx.x;          // 0..127  (k index)
    int r = c / 384;
    int rem = c % 384;
    int t = rem / 128;
    int j = rem % 128;
    const float* We = r ? We1 : We0;
    const float* be = r ? be1 : be0;
    const float* Wt = (t == 0) ? Wk : (t == 1) ? Wq : Wv;
    const float* bt = (t == 0) ? bk : (t == 1) ? bq : bv;
    const float scale = (t == 1) ? 0.125f : 1.0f;

    __shared__ float sWe[128];
    sWe[i] = We[i * 128 + j];
    __syncthreads();

    float acc = 0.f;
#pragma unroll 8
    for (int m = 0; m < 128; m++) acc += Wt[i * 128 + m] * sWe[m];
    float w = acc * scale;
    __nv_bfloat16 h = __float2bfloat16_rn(w);
    __nv_bfloat16 l = __float2bfloat16_rn(w - __bfloat162float(h));
    g_WCt_hi[c * 128 + i] = h;
    g_WCt_lo[c * 128 + i] = l;

    if (i == 0) {
        float b = 0.f;
        for (int m = 0; m < 128; m++) b += bt[m] * sWe[m];
        g_bc[c] = (b + be[j]) * scale;
    }
}

__global__ void prep_wo_kernel(const float* __restrict__ Wo) {
    int n = blockIdx.x;   // 0..127
    int i = threadIdx.x;  // 0..127 (k index)
    float w = Wo[i * 128 + n];
    __nv_bfloat16 h = __float2bfloat16_rn(w);
    __nv_bfloat16 l = __float2bfloat16_rn(w - __bfloat162float(h));
    g_Wot_hi[n * 128 + i] = h;
    g_Wot_lo[n * 128 + i] = l;
}

// ---------------- HMMA GEMM: C[M][COLS] = A[M][128] * Bt[COLS][128]^T + bias ----------------
// bf16x3 split (AhiBhi + AloBhi + AhiBlo), fp32 mma accumulators.
// CTA: 128 rows, persistent over NTILES column tiles of 128; B double-buffered cp.async.
// smem: AH 32K | AL 32K | B0H 32K | B0L 32K | B1H 32K | B1L 32K  (192 KB max)
// Swizzle: row of 256B = 16 chunks of 16B; chunk c stored at c ^ (row&7).
__global__ void __launch_bounds__(256) hgemm_kernel(
    const float* __restrict__ A,
    const __nv_bfloat16* __restrict__ BtH,
    const __nv_bfloat16* __restrict__ BtL,
    const float* __restrict__ bias,
    float* __restrict__ C,
    int COLS, int Mrows, int NTILES) {
    extern __shared__ char smem[];
    const uint32_t sb = smem_u32(smem);
    const int tid = threadIdx.x;
    const int m0 = blockIdx.x * 128;

    // issue B tile 0 loads first (overlaps with A conversion)
    auto loadB = [&](uint32_t dstH, uint32_t dstL, int n0) {
#pragma unroll
        for (int it = 0; it < 8; it++) {
            int u = tid + it * 256;          // 0..2047
            int row = u >> 4, kb = u & 15;
            uint32_t off = row * 256 + ((uint32_t)(kb ^ (row & 7)) << 4);
            const char* gh = (const char*)(BtH + (size_t)(n0 + row) * 128) + kb * 16;
            const char* gl = (const char*)(BtL + (size_t)(n0 + row) * 128) + kb * 16;
            CP_ASYNC16(dstH + off, gh);
            CP_ASYNC16(dstL + off, gl);
        }
        CP_COMMIT();
    };
    loadB(sb + 65536, sb + 98304, 0);

    // A tile: fp32 -> bf16 hi/lo, swizzled
#pragma unroll
    for (int it = 0; it < 8; it++) {
        int u = tid + it * 256;
        int row = u >> 4, kb = u & 15;
        int gr = m0 + row;
        float4 v0 = make_float4(0.f, 0.f, 0.f, 0.f), v1 = v0;
        if (gr < Mrows) {
            const float* p = A + (size_t)gr * 128 + kb * 8;
            v0 = *(const float4*)p;
            v1 = *(const float4*)(p + 4);
        }
        uint32_t h[4], l[4];
        split2(v0.x, v0.y, h[0], l[0]);
        split2(v0.z, v0.w, h[1], l[1]);
        split2(v1.x, v1.y, h[2], l[2]);
        split2(v1.z, v1.w, h[3], l[3]);
        uint32_t off = row * 256 + ((uint32_t)(kb ^ (row & 7)) << 4);
        *(uint4*)(smem + off) = make_uint4(h[0], h[1], h[2], h[3]);
        *(uint4*)(smem + 32768 + off) = make_uint4(l[0], l[1], l[2], l[3]);
    }

    // per-warp constants
    const int wid = tid >> 5, lane = tid & 31;
    const int wm = wid & 1, wn = wid >> 1;     // warp tile: 64 m x 32 n
    const uint32_t x7 = lane & 7;
    const uint32_t aRow = wm * 64 + (lane & 15);
    const uint32_t akoff = lane >> 4;
    const uint32_t bRow = wn * 32 + (lane & 7) + ((lane >> 4) << 3);
    const uint32_t bkoff = (lane >> 3) & 1;
    const uint32_t ah_base = sb + aRow * 256;
    const uint32_t al_base = sb + 32768 + aRow * 256;
    const int g = lane >> 2, tg = lane & 3;

    for (int nt = 0; nt < NTILES; nt++) {
        if (nt + 1 < NTILES) {
            uint32_t nb = sb + 65536 + ((nt + 1) & 1) * 65536;
            loadB(nb, nb + 32768, (nt + 1) * 128);
            CP_WAIT(1);
        } else {
            CP_WAIT(0);
        }
        __syncthreads();

        const uint32_t bufH = sb + 65536 + (nt & 1) * 65536;
        const uint32_t bh_base = bufH + bRow * 256;
        const uint32_t bl_base = bufH + 32768 + bRow * 256;

        float acc[4][4][4] = {};
#pragma unroll
        for (int kc = 0; kc < 8; kc++) {
            const uint32_t kxa = (((2 * kc + akoff) ^ x7) << 4);
            const uint32_t kxb = (((2 * kc + bkoff) ^ x7) << 4);
            uint32_t AH[4][4], AL[4][4], BH[2][4], BL[2][4];
#pragma unroll
            for (int ma = 0; ma < 4; ma++) LDSM4(AH[ma], ah_base + ma * 4096 + kxa);
#pragma unroll
            for (int nb = 0; nb < 2; nb++) LDSM4(BH[nb], bh_base + nb * 4096 + kxb);
#pragma unroll
            for (int ma = 0; ma < 4; ma++)
#pragma unroll
                for (int na = 0; na < 4; na++)
                    MMA(acc[ma][na], AH[ma], BH[na >> 1][(na & 1) * 2], BH[na >> 1][(na & 1) * 2 + 1]);
#pragma unroll
            for (int ma = 0; ma < 4; ma++) LDSM4(AL[ma], al_base + ma * 4096 + kxa);
#pragma unroll
            for (int ma = 0; ma < 4; ma++)
#pragma unroll
                for (int na = 0; na < 4; na++)
                    MMA(acc[ma][na], AL[ma], BH[na >> 1][(na & 1) * 2], BH[na >> 1][(na & 1) * 2 + 1]);
#pragma unroll
            for (int nb = 0; nb < 2; nb++) LDSM4(BL[nb], bl_base + nb * 4096 + kxb);
#pragma unroll
            for (int ma = 0; ma < 4; ma++)
#pragma unroll
                for (int na = 0; na < 4; na++)
                    MMA(acc[ma][na], AH[ma], BL[na >> 1][(na & 1) * 2], BL[na >> 1][(na & 1) * 2 + 1]);
        }

        // epilogue
        const int n0g = nt * 128;
#pragma unroll
        for (int ma = 0; ma < 4; ma++) {
            int row = m0 + wm * 64 + ma * 16 + g;
#pragma unroll
            for (int na = 0; na < 4; na++) {
                int col = n0g + wn * 32 + na * 8 + tg * 2;
                float2 bb = *(const float2*)(bias + col);
                float* c = acc[ma][na];
                if (row < Mrows) {
                    float2 o = make_float2(c[0] + bb.x, c[1] + bb.y);
                    *(float2*)(C + (size_t)row * COLS + col) = o;
                }
                if (row + 8 < Mrows) {
                    float2 o = make_float2(c[2] + bb.x, c[3] + bb.y);
                    *(float2*)(C + (size_t)(row + 8) * COLS + col) = o;
                }
            }
        }
        __syncthreads();
    }
}

// ---------------- edge pass A: e = exp(k[src].q[dst]) per head; s[dst] += e ----------------
__global__ void __launch_bounds__(256) edge_a_kernel(const int* __restrict__ src,
                                                     const int* __restrict__ dst, int rel) {
    int warp = (blockIdx.x * blockDim.x + threadIdx.x) >> 5;
    int lane = threadIdx.x & 31;
    if (warp >= N_EDGES) return;
    int sn = src[warp];
    int dn = dst[warp];
    const int rbase = rel * 384;
    const float4* kr = (const float4*)(g_KQV + (size_t)sn * KQV_COLS + rbase);
    const float4* qr = (const float4*)(g_KQV + (size_t)dn * KQV_COLS + rbase + 128);
    float4 a = kr[lane];
    float4 b = qr[lane];
    float p = a.x * b.x + a.y * b.y + a.z * b.z + a.w * b.w;
    p += __shfl_xor_sync(0xffffffffu, p, 1);
    p += __shfl_xor_sync(0xffffffffu, p, 2);
    p += __shfl_xor_sync(0xffffffffu, p, 4);
    p += __shfl_xor_sync(0xffffffffu, p, 8);
    float el = expf(p);
    float* s = g_s + rel * (N_NODES * 2);
    float* att = g_att + (size_t)rel * N_EDGES * 2;
    if (lane == 0) {
        att[(size_t)warp * 2 + 0] = el;
        atomicAdd(&s[dn * 2 + 0], el);
    }
    if (lane == 16) {
        att[(size_t)warp * 2 + 1] = el;
        atomicAdd(&s[dn * 2 + 1], el);
    }
}

// ---------------- edge pass B: upd[dst] += v[src] * (e / s[dst]) ----------------
__global__ void __launch_bounds__(256) edge_b_kernel(const int* __restrict__ src,
                                                     const int* __restrict__ dst, int rel) {
    int warp = (blockIdx.x * blockDim.x + threadIdx.x) >> 5;
    int lane = threadIdx.x & 31;
    if (warp >= N_EDGES) return;
    int sn = src[warp];
    int dn = dst[warp];
    const float* s = g_s + rel * (N_NODES * 2);
    const float* att = g_att + (size_t)rel * N_EDGES * 2;
    float w0 = att[(size_t)warp * 2 + 0] / s[dn * 2 + 0];
    float w1 = att[(size_t)warp * 2 + 1] / s[dn * 2 + 1];
    float w = (lane < 16) ? w0 : w1;
    const float4* vr = (const float4*)(g_KQV + (size_t)sn * KQV_COLS + rel * 384 + 256);
    float4 v = vr[lane];
    float* o = g_upd + (size_t)dn * DIM + lane * 4;
    atomicAdd(o + 0, v.x * w);
    atomicAdd(o + 1, v.y * w);
    atomicAdd(o + 2, v.z * w);
    atomicAdd(o + 3, v.w * w);
}

// ---------------- launch ----------------
extern "C" void kernel_launch(void* const* d_in, const int* in_sizes, int n_in,
                              void* d_out, int out_size) {
    const float* feat = (const float*)d_in[0];
    const int* src0 = (const int*)d_in[1];
    const int* dst0 = (const int*)d_in[2];
    const int* src1 = (const int*)d_in[3];
    const int* dst1 = (const int*)d_in[4];
    const float* Wk = (const float*)d_in[5];
    const float* bk = (const float*)d_in[6];
    const float* Wq = (const float*)d_in[7];
    const float* bq = (const float*)d_in[8];
    const float* Wv = (const float*)d_in[9];
    const float* bv = (const float*)d_in[10];
    const float* Wo = (const float*)d_in[11];
    const float* bo = (const float*)d_in[12];
    const float* We0 = (const float*)d_in[13];
    const float* be0 = (const float*)d_in[14];
    const float* We1 = (const float*)d_in[15];
    const float* be1 = (const float*)d_in[16];
    float* out = (float*)d_out;

    void *pbc, *pKQV, *pupd, *pWCh, *pWCl, *pWoh, *pWol;
    cudaGetSymbolAddress(&pbc, g_bc);
    cudaGetSymbolAddress(&pKQV, g_KQV);
    cudaGetSymbolAddress(&pupd, g_upd);
    cudaGetSymbolAddress(&pWCh, g_WCt_hi);
    cudaGetSymbolAddress(&pWCl, g_WCt_lo);
    cudaGetSymbolAddress(&pWoh, g_Wot_hi);
    cudaGetSymbolAddress(&pWol, g_Wot_lo);

    cudaFuncSetAttribute(hgemm_kernel, cudaFuncAttributeMaxDynamicSharedMemorySize, 196608);

    zero_kernel<<<2048, 256>>>();
    prep_kernel<<<KQV_COLS, 128>>>(Wk, bk, Wq, bq, Wv, bv, We0, be0, We1, be1);
    prep_wo_kernel<<<128, 128>>>(Wo);

    const int Mtiles = (N_NODES + 127) / 128;  // 1563

    // KQV = feat @ WC + bc   ([200000,128] x [128,768])
    hgemm_kernel<<<Mtiles, 256, 196608>>>(
        feat, (const __nv_bfloat16*)pWCh, (const __nv_bfloat16*)pWCl,
        (const float*)pbc, (float*)pKQV, KQV_COLS, N_NODES, 6);

    const int eblocks = N_EDGES / 8;
    edge_a_kernel<<<eblocks, 256>>>(src0, dst0, 0);
    edge_a_kernel<<<eblocks, 256>>>(src1, dst1, 1);
    edge_b_kernel<<<eblocks, 256>>>(src0, dst0, 0);
    edge_b_kernel<<<eblocks, 256>>>(src1, dst1, 1);

    // out = upd @ Wo + bo    ([200000,128] x [128,128])
    hgemm_kernel<<<Mtiles, 256, 131072>>>(
        (const float*)pupd, (const __nv_bfloat16*)pWoh, (const __nv_bfloat16*)pWol,
        bo, out, DIM, N_NODES, 1);
}

// round 4
// speedup vs baseline: 2.1604x; 1.0101x over previous
#include <cuda_runtime.h>
#include <cuda_bf16.h>
#include <stdint.h>
#include <math.h>

#define N_NODES 200000
#define N_EDGES 500000
#define DIM 128
#define KQV_COLS 768   // [k0 q0 v0 | k1 q1 v1]

// ---------------- scratch (device globals; no allocation allowed) ----------------
__device__ __align__(16) float g_bc[KQV_COLS];                       // fused bias
__device__ __align__(16) __nv_bfloat16 g_WCt_hi[KQV_COLS * 128];     // fused W^T [n][k]
__device__ __align__(16) __nv_bfloat16 g_WCt_lo[KQV_COLS * 128];
__device__ __align__(16) __nv_bfloat16 g_Wot_hi[128 * 128];          // Wo^T [n][k]
__device__ __align__(16) __nv_bfloat16 g_Wot_lo[128 * 128];
__device__ __align__(16) float g_KQV[(size_t)N_NODES * KQV_COLS];    // 614 MB
__device__ __align__(16) float g_upd[(size_t)N_NODES * DIM];         // 102 MB
__device__ __align__(16) float g_s[2 * N_NODES * 2];                 // per-rel segment sums
__device__ __align__(16) float g_att[2 * (size_t)N_EDGES * 2];       // per-rel exp(logit)

// ---------------- helpers ----------------
static __device__ __forceinline__ uint32_t smem_u32(const void* p) {
    uint32_t a;
    asm("{ .reg .u64 t; cvta.to.shared.u64 t, %1; cvt.u32.u64 %0, t; }" : "=r"(a) : "l"(p));
    return a;
}
static __device__ __forceinline__ uint32_t pack2(__nv_bfloat16 a, __nv_bfloat16 b) {
    uint16_t ua = *(uint16_t*)&a, ub = *(uint16_t*)&b;
    return (uint32_t)ua | ((uint32_t)ub << 16);
}
static __device__ __forceinline__ void split2(float a, float b, uint32_t& h, uint32_t& l) {
    __nv_bfloat16 ha = __float2bfloat16_rn(a), hb = __float2bfloat16_rn(b);
    float ra = a - __bfloat162float(ha), rb = b - __bfloat162float(hb);
    h = pack2(ha, hb);
    l = pack2(__float2bfloat16_rn(ra), __float2bfloat16_rn(rb));
}

#define LDSM4(r, addr)                                                           \
    asm volatile("ldmatrix.sync.aligned.m8n8.x4.shared.b16 {%0,%1,%2,%3}, [%4];" \
                 : "=r"((r)[0]), "=r"((r)[1]), "=r"((r)[2]), "=r"((r)[3])        \
                 : "r"(addr))

#define MMA(c, a, b0, b1)                                                     \
    asm volatile(                                                             \
        "mma.sync.aligned.m16n8k16.row.col.f32.bf16.bf16.f32 "                \
        "{%0,%1,%2,%3},{%4,%5,%6,%7},{%8,%9},{%0,%1,%2,%3};"                  \
        : "+f"((c)[0]), "+f"((c)[1]), "+f"((c)[2]), "+f"((c)[3])              \
        : "r"((a)[0]), "r"((a)[1]), "r"((a)[2]), "r"((a)[3]), "r"(b0), "r"(b1))

#define CP_ASYNC16(dst, src) \
    asm volatile("cp.async.ca.shared.global [%0], [%1], 16;" :: "r"(dst), "l"(src))
#define CP_COMMIT() asm volatile("cp.async.commit_group;")
#define CP_WAIT(n) asm volatile("cp.async.wait_group %0;" :: "n"(n))

// ---------------- zero scratch that is accumulated into ----------------
__global__ void zero_kernel() {
    size_t i0 = blockIdx.x * (size_t)blockDim.x + threadIdx.x;
    size_t stride = gridDim.x * (size_t)blockDim.x;
    float4* u = (float4*)g_upd;
    const size_t nu = (size_t)N_NODES * DIM / 4;
    for (size_t i = i0; i < nu; i += stride) u[i] = make_float4(0.f, 0.f, 0.f, 0.f);
    float4* s = (float4*)g_s;
    const size_t ns = (size_t)2 * N_NODES * 2 / 4;
    for (size_t i = i0; i < ns; i += stride) s[i] = make_float4(0.f, 0.f, 0.f, 0.f);
}

// ---------------- fold node-type + edge-type linears; emit bf16 hi/lo transposed ----------------
__global__ void prep_kernel(const float* __restrict__ Wk, const float* __restrict__ bk,
                            const float* __restrict__ Wq, const float* __restrict__ bq,
                            const float* __restrict__ Wv, const float* __restrict__ bv,
                            const float* __restrict__ We0, const float* __restrict__ be0,
                            const float* __restrict__ We1, const float* __restrict__ be1) {
    int c = blockIdx.x;           // 0..767
    int i = threadIdx.x;          // 0..127  (k index)
    int r = c / 384;
    int rem = c % 384;
    int t = rem / 128;
    int j = rem % 128;
    const float* We = r ? We1 : We0;
    const float* be = r ? be1 : be0;
    const float* Wt = (t == 0) ? Wk : (t == 1) ? Wq : Wv;
    const float* bt = (t == 0) ? bk : (t == 1) ? bq : bv;
    const float scale = (t == 1) ? 0.125f : 1.0f;

    __shared__ float sWe[128];
    sWe[i] = We[i * 128 + j];
    __syncthreads();

    float acc = 0.f;
#pragma unroll 8
    for (int m = 0; m < 128; m++) acc += Wt[i * 128 + m] * sWe[m];
    float w = acc * scale;
    __nv_bfloat16 h = __float2bfloat16_rn(w);
    __nv_bfloat16 l = __float2bfloat16_rn(w - __bfloat162float(h));
    g_WCt_hi[c * 128 + i] = h;
    g_WCt_lo[c * 128 + i] = l;

    if (i == 0) {
        float b = 0.f;
        for (int m = 0; m < 128; m++) b += bt[m] * sWe[m];
        g_bc[c] = (b + be[j]) * scale;
    }
}

__global__ void prep_wo_kernel(const float* __restrict__ Wo) {
    int n = blockIdx.x;   // 0..127
    int i = threadIdx.x;  // 0..127 (k index)
    float w = Wo[i * 128 + n];
    __nv_bfloat16 h = __float2bfloat16_rn(w);
    __nv_bfloat16 l = __float2bfloat16_rn(w - __bfloat162float(h));
    g_Wot_hi[n * 128 + i] = h;
    g_Wot_lo[n * 128 + i] = l;
}

// ---------------- HMMA GEMM: C[M][COLS] = A[M][128] * Bt[COLS][128]^T + bias ----------------
// bf16x3 split (AhiBhi + AloBhi + AhiBlo), fp32 mma accumulators.
// CTA: 512 threads (16 warps, 4/SMSP), 128 rows, persistent over NTILES col-tiles of 128.
// Warp tile 32m x 32n. B double-buffered via cp.async.
// smem: AH 32K | AL 32K | B0H 32K | B0L 32K | B1H 32K | B1L 32K  (192 KB max)
// Swizzle: row of 256B = 16 chunks of 16B; chunk c stored at c ^ (row&7).
__global__ void __launch_bounds__(512) hgemm_kernel(
    const float* __restrict__ A,
    const __nv_bfloat16* __restrict__ BtH,
    const __nv_bfloat16* __restrict__ BtL,
    const float* __restrict__ bias,
    float* __restrict__ C,
    int COLS, int Mrows, int NTILES) {
    extern __shared__ char smem[];
    const uint32_t sb = smem_u32(smem);
    const int tid = threadIdx.x;
    const int m0 = blockIdx.x * 128;

    // issue B tile 0 loads first (overlaps with A conversion)
    auto loadB = [&](uint32_t dstH, uint32_t dstL, int n0) {
#pragma unroll
        for (int it = 0; it < 4; it++) {
            int u = tid + it * 512;          // 0..2047
            int row = u >> 4, kb = u & 15;
            uint32_t off = row * 256 + ((uint32_t)(kb ^ (row & 7)) << 4);
            const char* gh = (const char*)(BtH + (size_t)(n0 + row) * 128) + kb * 16;
            const char* gl = (const char*)(BtL + (size_t)(n0 + row) * 128) + kb * 16;
            CP_ASYNC16(dstH + off, gh);
            CP_ASYNC16(dstL + off, gl);
        }
        CP_COMMIT();
    };
    loadB(sb + 65536, sb + 98304, 0);

    // A tile: fp32 -> bf16 hi/lo, swizzled
#pragma unroll
    for (int it = 0; it < 4; it++) {
        int u = tid + it * 512;
        int row = u >> 4, kb = u & 15;
        int gr = m0 + row;
        float4 v0 = make_float4(0.f, 0.f, 0.f, 0.f), v1 = v0;
        if (gr < Mrows) {
            const float* p = A + (size_t)gr * 128 + kb * 8;
            v0 = *(const float4*)p;
            v1 = *(const float4*)(p + 4);
        }
        uint32_t h[4], l[4];
        split2(v0.x, v0.y, h[0], l[0]);
        split2(v0.z, v0.w, h[1], l[1]);
        split2(v1.x, v1.y, h[2], l[2]);
        split2(v1.z, v1.w, h[3], l[3]);
        uint32_t off = row * 256 + ((uint32_t)(kb ^ (row & 7)) << 4);
        *(uint4*)(smem + off) = make_uint4(h[0], h[1], h[2], h[3]);
        *(uint4*)(smem + 32768 + off) = make_uint4(l[0], l[1], l[2], l[3]);
    }

    // per-warp constants: 16 warps -> 4x4 grid of 32m x 32n warp tiles
    const int wid = tid >> 5, lane = tid & 31;
    const int wm = wid & 3, wn = wid >> 2;
    const uint32_t x7 = lane & 7;
    const uint32_t aRow = wm * 32 + (lane & 15);
    const uint32_t akoff = lane >> 4;
    const uint32_t bRow = wn * 32 + (lane & 7) + ((lane >> 4) << 3);
    const uint32_t bkoff = (lane >> 3) & 1;
    const uint32_t ah_base = sb + aRow * 256;
    const uint32_t al_base = sb + 32768 + aRow * 256;
    const int g = lane >> 2, tg = lane & 3;

    for (int nt = 0; nt < NTILES; nt++) {
        if (nt + 1 < NTILES) {
            uint32_t nb = sb + 65536 + ((nt + 1) & 1) * 65536;
            loadB(nb, nb + 32768, (nt + 1) * 128);
            CP_WAIT(1);
        } else {
            CP_WAIT(0);
        }
        __syncthreads();

        const uint32_t bufH = sb + 65536 + (nt & 1) * 65536;
        const uint32_t bh_base = bufH + bRow * 256;
        const uint32_t bl_base = bufH + 32768 + bRow * 256;

        float acc[2][4][4] = {};
#pragma unroll
        for (int kc = 0; kc < 8; kc++) {
            const uint32_t kxa = (((2 * kc + akoff) ^ x7) << 4);
            const uint32_t kxb = (((2 * kc + bkoff) ^ x7) << 4);
            uint32_t AH[2][4], AL[2][4], BH[2][4], BL[2][4];
#pragma unroll
            for (int ma = 0; ma < 2; ma++) LDSM4(AH[ma], ah_base + ma * 4096 + kxa);
#pragma unroll
            for (int nb = 0; nb < 2; nb++) LDSM4(BH[nb], bh_base + nb * 4096 + kxb);
#pragma unroll
            for (int ma = 0; ma < 2; ma++) LDSM4(AL[ma], al_base + ma * 4096 + kxa);
#pragma unroll
            for (int nb = 0; nb < 2; nb++) LDSM4(BL[nb], bl_base + nb * 4096 + kxb);
#pragma unroll
            for (int ma = 0; ma < 2; ma++)
#pragma unroll
                for (int na = 0; na < 4; na++)
                    MMA(acc[ma][na], AH[ma], BH[na >> 1][(na & 1) * 2], BH[na >> 1][(na & 1) * 2 + 1]);
#pragma unroll
            for (int ma = 0; ma < 2; ma++)
#pragma unroll
                for (int na = 0; na < 4; na++)
                    MMA(acc[ma][na], AL[ma], BH[na >> 1][(na & 1) * 2], BH[na >> 1][(na & 1) * 2 + 1]);
#pragma unroll
            for (int ma = 0; ma < 2; ma++)
#pragma unroll
                for (int na = 0; na < 4; na++)
                    MMA(acc[ma][na], AH[ma], BL[na >> 1][(na & 1) * 2], BL[na >> 1][(na & 1) * 2 + 1]);
        }

        // epilogue
        const int n0g = nt * 128;
#pragma unroll
        for (int ma = 0; ma < 2; ma++) {
            int row = m0 + wm * 32 + ma * 16 + g;
#pragma unroll
            for (int na = 0; na < 4; na++) {
                int col = n0g + wn * 32 + na * 8 + tg * 2;
                float2 bb = *(const float2*)(bias + col);
                float* c = acc[ma][na];
                if (row < Mrows) {
                    float2 o = make_float2(c[0] + bb.x, c[1] + bb.y);
                    *(float2*)(C + (size_t)row * COLS + col) = o;
                }
                if (row + 8 < Mrows) {
                    float2 o = make_float2(c[2] + bb.x, c[3] + bb.y);
                    *(float2*)(C + (size_t)(row + 8) * COLS + col) = o;
                }
            }
        }
        __syncthreads();
    }
}

// ---------------- edge pass A (both relations): e = exp(k[src].q[dst]); s[dst] += e ----------------
__global__ void __launch_bounds__(256) edge_a_kernel(const int* __restrict__ src0,
                                                     const int* __restrict__ dst0,
                                                     const int* __restrict__ src1,
                                                     const int* __restrict__ dst1) {
    int warp = (blockIdx.x * blockDim.x + threadIdx.x) >> 5;
    int lane = threadIdx.x & 31;
    if (warp >= N_EDGES) return;
    int rel = blockIdx.y;
    const int* src = rel ? src1 : src0;
    const int* dst = rel ? dst1 : dst0;
    int sn = src[warp];
    int dn = dst[warp];
    const int rbase = rel * 384;
    const float4* kr = (const float4*)(g_KQV + (size_t)sn * KQV_COLS + rbase);
    const float4* qr = (const float4*)(g_KQV + (size_t)dn * KQV_COLS + rbase + 128);
    float4 a = kr[lane];
    float4 b = qr[lane];
    float p = a.x * b.x + a.y * b.y + a.z * b.z + a.w * b.w;
    p += __shfl_xor_sync(0xffffffffu, p, 1);
    p += __shfl_xor_sync(0xffffffffu, p, 2);
    p += __shfl_xor_sync(0xffffffffu, p, 4);
    p += __shfl_xor_sync(0xffffffffu, p, 8);
    float el = expf(p);
    float* s = g_s + rel * (N_NODES * 2);
    float* att = g_att + (size_t)rel * N_EDGES * 2;
    if (lane == 0) {
        att[(size_t)warp * 2 + 0] = el;
        atomicAdd(&s[dn * 2 + 0], el);
    }
    if (lane == 16) {
        att[(size_t)warp * 2 + 1] = el;
        atomicAdd(&s[dn * 2 + 1], el);
    }
}

// ---------------- edge pass B (both relations): upd[dst] += v[src] * (e / s[dst]) ----------------
__global__ void __launch_bounds__(256) edge_b_kernel(const int* __restrict__ src0,
                                                     const int* __restrict__ dst0,
                                                     const int* __restrict__ src1,
                                                     const int* __restrict__ dst1) {
    int warp = (blockIdx.x * blockDim.x + threadIdx.x) >> 5;
    int lane = threadIdx.x & 31;
    if (warp >= N_EDGES) return;
    int rel = blockIdx.y;
    const int* src = rel ? src1 : src0;
    const int* dst = rel ? dst1 : dst0;
    int sn = src[warp];
    int dn = dst[warp];
    const float* s = g_s + rel * (N_NODES * 2);
    const float* att = g_att + (size_t)rel * N_EDGES * 2;
    float w0 = att[(size_t)warp * 2 + 0] / s[dn * 2 + 0];
    float w1 = att[(size_t)warp * 2 + 1] / s[dn * 2 + 1];
    float w = (lane < 16) ? w0 : w1;
    const float4* vr = (const float4*)(g_KQV + (size_t)sn * KQV_COLS + rel * 384 + 256);
    float4 v = vr[lane];
    float* o = g_upd + (size_t)dn * DIM + lane * 4;
    atomicAdd(o + 0, v.x * w);
    atomicAdd(o + 1, v.y * w);
    atomicAdd(o + 2, v.z * w);
    atomicAdd(o + 3, v.w * w);
}

// ---------------- launch ----------------
extern "C" void kernel_launch(void* const* d_in, const int* in_sizes, int n_in,
                              void* d_out, int out_size) {
    const float* feat = (const float*)d_in[0];
    const int* src0 = (const int*)d_in[1];
    const int* dst0 = (const int*)d_in[2];
    const int* src1 = (const int*)d_in[3];
    const int* dst1 = (const int*)d_in[4];
    const float* Wk = (const float*)d_in[5];
    const float* bk = (const float*)d_in[6];
    const float* Wq = (const float*)d_in[7];
    const float* bq = (const float*)d_in[8];
    const float* Wv = (const float*)d_in[9];
    const float* bv = (const float*)d_in[10];
    const float* Wo = (const float*)d_in[11];
    const float* bo = (const float*)d_in[12];
    const float* We0 = (const float*)d_in[13];
    const float* be0 = (const float*)d_in[14];
    const float* We1 = (const float*)d_in[15];
    const float* be1 = (const float*)d_in[16];
    float* out = (float*)d_out;

    void *pbc, *pKQV, *pupd, *pWCh, *pWCl, *pWoh, *pWol;
    cudaGetSymbolAddress(&pbc, g_bc);
    cudaGetSymbolAddress(&pKQV, g_KQV);
    cudaGetSymbolAddress(&pupd, g_upd);
    cudaGetSymbolAddress(&pWCh, g_WCt_hi);
    cudaGetSymbolAddress(&pWCl, g_WCt_lo);
    cudaGetSymbolAddress(&pWoh, g_Wot_hi);
    cudaGetSymbolAddress(&pWol, g_Wot_lo);

    cudaFuncSetAttribute(hgemm_kernel, cudaFuncAttributeMaxDynamicSharedMemorySize, 196608);

    zero_kernel<<<2048, 256>>>();
    prep_kernel<<<KQV_COLS, 128>>>(Wk, bk, Wq, bq, Wv, bv, We0, be0, We1, be1);
    prep_wo_kernel<<<128, 128>>>(Wo);

    const int Mtiles = (N_NODES + 127) / 128;  // 1563

    // KQV = feat @ WC + bc   ([200000,128] x [128,768])
    hgemm_kernel<<<Mtiles, 512, 196608>>>(
        feat, (const __nv_bfloat16*)pWCh, (const __nv_bfloat16*)pWCl,
        (const float*)pbc, (float*)pKQV, KQV_COLS, N_NODES, 6);

    const int eblocks = N_EDGES / 8;
    edge_a_kernel<<<dim3(eblocks, 2), 256>>>(src0, dst0, src1, dst1);
    edge_b_kernel<<<dim3(eblocks, 2), 256>>>(src0, dst0, src1, dst1);

    // out = upd @ Wo + bo    ([200000,128] x [128,128])
    hgemm_kernel<<<Mtiles, 512, 131072>>>(
        (const float*)pupd, (const __nv_bfloat16*)pWoh, (const __nv_bfloat16*)pWol,
        bo, out, DIM, N_NODES, 1);
}

// round 5
// speedup vs baseline: 2.2834x; 1.0569x over previous
#include <cuda_runtime.h>
#include <cuda_bf16.h>
#include <cuda_fp16.h>
#include <stdint.h>
#include <math.h>

#define N_NODES 200000
#define N_EDGES 500000
#define DIM 128
#define KQV_COLS 768   // bias layout: [k0 q0 v0 | k1 q1 v1]

// ---------------- scratch (device globals; no allocation allowed) ----------------
__device__ __align__(16) float g_bc[KQV_COLS];                       // fused bias
__device__ __align__(16) __nv_bfloat16 g_WCt_hi[KQV_COLS * 128];     // fused W^T [n][k]
__device__ __align__(16) __nv_bfloat16 g_WCt_lo[KQV_COLS * 128];
__device__ __align__(16) __nv_bfloat16 g_Wot_hi[128 * 128];          // Wo^T [n][k]
__device__ __align__(16) __nv_bfloat16 g_Wot_lo[128 * 128];
__device__ __align__(16) __half g_K[2 * (size_t)N_NODES * 128];      // fp16 K per rel
__device__ __align__(16) __half g_Q[2 * (size_t)N_NODES * 128];      // fp16 Q per rel (scaled)
__device__ __align__(16) float g_V[2 * (size_t)N_NODES * 128];       // fp32 V per rel
__device__ __align__(16) float g_upd[(size_t)N_NODES * DIM];
__device__ __align__(16) float g_s[2 * N_NODES * 2];                 // per-rel segment sums
__device__ __align__(16) float g_att[2 * (size_t)N_EDGES * 2];       // per-rel exp(logit)

// ---------------- helpers ----------------
static __device__ __forceinline__ uint32_t smem_u32(const void* p) {
    uint32_t a;
    asm("{ .reg .u64 t; cvta.to.shared.u64 t, %1; cvt.u32.u64 %0, t; }" : "=r"(a) : "l"(p));
    return a;
}
static __device__ __forceinline__ uint32_t pack2(__nv_bfloat16 a, __nv_bfloat16 b) {
    uint16_t ua = *(uint16_t*)&a, ub = *(uint16_t*)&b;
    return (uint32_t)ua | ((uint32_t)ub << 16);
}
static __device__ __forceinline__ void split2(float a, float b, uint32_t& h, uint32_t& l) {
    __nv_bfloat16 ha = __float2bfloat16_rn(a), hb = __float2bfloat16_rn(b);
    float ra = a - __bfloat162float(ha), rb = b - __bfloat162float(hb);
    h = pack2(ha, hb);
    l = pack2(__float2bfloat16_rn(ra), __float2bfloat16_rn(rb));
}

#define LDSM4(r, addr)                                                           \
    asm volatile("ldmatrix.sync.aligned.m8n8.x4.shared.b16 {%0,%1,%2,%3}, [%4];" \
                 : "=r"((r)[0]), "=r"((r)[1]), "=r"((r)[2]), "=r"((r)[3])        \
                 : "r"(addr))

#define MMA(c, a, b0, b1)                                                     \
    asm volatile(                                                             \
        "mma.sync.aligned.m16n8k16.row.col.f32.bf16.bf16.f32 "                \
        "{%0,%1,%2,%3},{%4,%5,%6,%7},{%8,%9},{%0,%1,%2,%3};"                  \
        : "+f"((c)[0]), "+f"((c)[1]), "+f"((c)[2]), "+f"((c)[3])              \
        : "r"((a)[0]), "r"((a)[1]), "r"((a)[2]), "r"((a)[3]), "r"(b0), "r"(b1))

#define CP_ASYNC16(dst, src) \
    asm volatile("cp.async.ca.shared.global [%0], [%1], 16;" :: "r"(dst), "l"(src))
#define CP_COMMIT() asm volatile("cp.async.commit_group;")
#define CP_WAIT0() asm volatile("cp.async.wait_group 0;")

// ---------------- zero scratch that is accumulated into ----------------
__global__ void zero_kernel() {
    size_t i0 = blockIdx.x * (size_t)blockDim.x + threadIdx.x;
    size_t stride = gridDim.x * (size_t)blockDim.x;
    float4* u = (float4*)g_upd;
    const size_t nu = (size_t)N_NODES * DIM / 4;
    for (size_t i = i0; i < nu; i += stride) u[i] = make_float4(0.f, 0.f, 0.f, 0.f);
    float4* s = (float4*)g_s;
    const size_t ns = (size_t)2 * N_NODES * 2 / 4;
    for (size_t i = i0; i < ns; i += stride) s[i] = make_float4(0.f, 0.f, 0.f, 0.f);
}

// ---------------- fold node-type + edge-type linears; emit bf16 hi/lo transposed ----------------
__global__ void prep_kernel(const float* __restrict__ Wk, const float* __restrict__ bk,
                            const float* __restrict__ Wq, const float* __restrict__ bq,
                            const float* __restrict__ Wv, const float* __restrict__ bv,
                            const float* __restrict__ We0, const float* __restrict__ be0,
                            const float* __restrict__ We1, const float* __restrict__ be1) {
    int c = blockIdx.x;           // 0..767
    int i = threadIdx.x;          // 0..127  (k index)
    int r = c / 384;
    int rem = c % 384;
    int t = rem / 128;
    int j = rem % 128;
    const float* We = r ? We1 : We0;
    const float* be = r ? be1 : be0;
    const float* Wt = (t == 0) ? Wk : (t == 1) ? Wq : Wv;
    const float* bt = (t == 0) ? bk : (t == 1) ? bq : bv;
    const float scale = (t == 1) ? 0.125f : 1.0f;

    __shared__ float sWe[128];
    sWe[i] = We[i * 128 + j];
    __syncthreads();

    float acc = 0.f;
#pragma unroll 8
    for (int m = 0; m < 128; m++) acc += Wt[i * 128 + m] * sWe[m];
    float w = acc * scale;
    __nv_bfloat16 h = __float2bfloat16_rn(w);
    __nv_bfloat16 l = __float2bfloat16_rn(w - __bfloat162float(h));
    g_WCt_hi[c * 128 + i] = h;
    g_WCt_lo[c * 128 + i] = l;

    if (i == 0) {
        float b = 0.f;
        for (int m = 0; m < 128; m++) b += bt[m] * sWe[m];
        g_bc[c] = (b + be[j]) * scale;
    }
}

__global__ void prep_wo_kernel(const float* __restrict__ Wo) {
    int n = blockIdx.x;   // 0..127
    int i = threadIdx.x;  // 0..127 (k index)
    float w = Wo[i * 128 + n];
    __nv_bfloat16 h = __float2bfloat16_rn(w);
    __nv_bfloat16 l = __float2bfloat16_rn(w - __bfloat162float(h));
    g_Wot_hi[n * 128 + i] = h;
    g_Wot_lo[n * 128 + i] = l;
}

// ---------------- HMMA GEMM: [Mrows,128] x [128, NTILES*128] + bias ----------------
// bf16x3 split, fp32 accum. CTA: 256 threads (8 warps), 64 rows, 96KB smem -> 2 CTAs/SM.
// B single-buffered (the co-resident CTA hides the load).
// route=0: write fp32 to C (stride COLS). route=1: per-tile KQV routing (K,Q fp16; V fp32).
__global__ void __launch_bounds__(256) hgemm_kernel(
    const float* __restrict__ A,
    const __nv_bfloat16* __restrict__ BtH,
    const __nv_bfloat16* __restrict__ BtL,
    const float* __restrict__ bias,
    float* __restrict__ C,
    int COLS, int Mrows, int NTILES, int route) {
    extern __shared__ char smem[];
    const uint32_t sb = smem_u32(smem);
    const int tid = threadIdx.x;
    const int m0 = blockIdx.x * 64;
    const int SM_AL = 16384, SM_BH = 32768, SM_BL = 65536;

    auto loadB = [&](int n0) {
#pragma unroll
        for (int it = 0; it < 8; it++) {
            int u = tid + it * 256;          // 0..2047
            int row = u >> 4, kb = u & 15;
            uint32_t off = row * 256 + ((uint32_t)(kb ^ (row & 7)) << 4);
            const char* gh = (const char*)(BtH + (size_t)(n0 + row) * 128) + kb * 16;
            const char* gl = (const char*)(BtL + (size_t)(n0 + row) * 128) + kb * 16;
            CP_ASYNC16(sb + SM_BH + off, gh);
            CP_ASYNC16(sb + SM_BL + off, gl);
        }
        CP_COMMIT();
    };
    loadB(0);

    // A tile: 64 rows, fp32 -> bf16 hi/lo, swizzled
#pragma unroll
    for (int it = 0; it < 4; it++) {
        int u = tid + it * 256;              // 0..1023
        int row = u >> 4, kb = u & 15;
        int gr = m0 + row;
        float4 v0 = make_float4(0.f, 0.f, 0.f, 0.f), v1 = v0;
        if (gr < Mrows) {
            const float* p = A + (size_t)gr * 128 + kb * 8;
            v0 = *(const float4*)p;
            v1 = *(const float4*)(p + 4);
        }
        uint32_t h[4], l[4];
        split2(v0.x, v0.y, h[0], l[0]);
        split2(v0.z, v0.w, h[1], l[1]);
        split2(v1.x, v1.y, h[2], l[2]);
        split2(v1.z, v1.w, h[3], l[3]);
        uint32_t off = row * 256 + ((uint32_t)(kb ^ (row & 7)) << 4);
        *(uint4*)(smem + off) = make_uint4(h[0], h[1], h[2], h[3]);
        *(uint4*)(smem + SM_AL + off) = make_uint4(l[0], l[1], l[2], l[3]);
    }

    // 8 warps -> 2m x 4n grid of 32x32 warp tiles
    const int wid = tid >> 5, lane = tid & 31;
    const int wm = wid & 1, wn = wid >> 1;
    const uint32_t x7 = lane & 7;
    const uint32_t aRow = wm * 32 + (lane & 15);
    const uint32_t akoff = lane >> 4;
    const uint32_t bRow = wn * 32 + (lane & 7) + ((lane >> 4) << 3);
    const uint32_t bkoff = (lane >> 3) & 1;
    const uint32_t ah_base = sb + aRow * 256;
    const uint32_t al_base = sb + SM_AL + aRow * 256;
    const uint32_t bh_base = sb + SM_BH + bRow * 256;
    const uint32_t bl_base = sb + SM_BL + bRow * 256;
    const int g = lane >> 2, tg = lane & 3;

    for (int nt = 0; nt < NTILES; nt++) {
        CP_WAIT0();
        __syncthreads();

        float acc[2][4][4] = {};
#pragma unroll
        for (int kc = 0; kc < 8; kc++) {
            const uint32_t kxa = (((2 * kc + akoff) ^ x7) << 4);
            const uint32_t kxb = (((2 * kc + bkoff) ^ x7) << 4);
            uint32_t AH[2][4], AL[2][4], BH[2][4], BL[2][4];
#pragma unroll
            for (int ma = 0; ma < 2; ma++) LDSM4(AH[ma], ah_base + ma * 4096 + kxa);
#pragma unroll
            for (int nb = 0; nb < 2; nb++) LDSM4(BH[nb], bh_base + nb * 4096 + kxb);
#pragma unroll
            for (int ma = 0; ma < 2; ma++) LDSM4(AL[ma], al_base + ma * 4096 + kxa);
#pragma unroll
            for (int nb = 0; nb < 2; nb++) LDSM4(BL[nb], bl_base + nb * 4096 + kxb);
#pragma unroll
            for (int ma = 0; ma < 2; ma++)
#pragma unroll
                for (int na = 0; na < 4; na++)
                    MMA(acc[ma][na], AH[ma], BH[na >> 1][(na & 1) * 2], BH[na >> 1][(na & 1) * 2 + 1]);
#pragma unroll
            for (int ma = 0; ma < 2; ma++)
#pragma unroll
                for (int na = 0; na < 4; na++)
                    MMA(acc[ma][na], AL[ma], BH[na >> 1][(na & 1) * 2], BH[na >> 1][(na & 1) * 2 + 1]);
#pragma unroll
            for (int ma = 0; ma < 2; ma++)
#pragma unroll
                for (int na = 0; na < 4; na++)
                    MMA(acc[ma][na], AH[ma], BL[na >> 1][(na & 1) * 2], BL[na >> 1][(na & 1) * 2 + 1]);
        }

        // prefetch next B after all warps finished reading this one
        __syncthreads();
        if (nt + 1 < NTILES) loadB((nt + 1) * 128);

        // ---- epilogue ----
        if (route == 0) {
#pragma unroll
            for (int ma = 0; ma < 2; ma++) {
                int row = m0 + wm * 32 + ma * 16 + g;
#pragma unroll
                for (int na = 0; na < 4; na++) {
                    int col = nt * 128 + wn * 32 + na * 8 + tg * 2;
                    float2 bb = *(const float2*)(bias + col);
                    float* c = acc[ma][na];
                    if (row < Mrows)
                        *(float2*)(C + (size_t)row * COLS + col) =
                            make_float2(c[0] + bb.x, c[1] + bb.y);
                    if (row + 8 < Mrows)
                        *(float2*)(C + (size_t)(row + 8) * COLS + col) =
                            make_float2(c[2] + bb.x, c[3] + bb.y);
                }
            }
        } else {
            int r = nt / 3, t = nt - r * 3;
            float* vout = g_V + (size_t)r * N_NODES * 128;
            __half* hout = (t == 0 ? g_K : g_Q) + (size_t)r * N_NODES * 128;
#pragma unroll
            for (int ma = 0; ma < 2; ma++) {
                int row = m0 + wm * 32 + ma * 16 + g;
#pragma unroll
                for (int na = 0; na < 4; na++) {
                    int j = wn * 32 + na * 8 + tg * 2;
                    float2 bb = *(const float2*)(bias + nt * 128 + j);
                    float* c = acc[ma][na];
                    float2 o0 = make_float2(c[0] + bb.x, c[1] + bb.y);
                    float2 o1 = make_float2(c[2] + bb.x, c[3] + bb.y);
                    if (t == 2) {
                        if (row < Mrows) *(float2*)(vout + (size_t)row * 128 + j) = o0;
                        if (row + 8 < Mrows) *(float2*)(vout + (size_t)(row + 8) * 128 + j) = o1;
                    } else {
                        if (row < Mrows)
                            *(__half2*)(hout + (size_t)row * 128 + j) = __float22half2_rn(o0);
                        if (row + 8 < Mrows)
                            *(__half2*)(hout + (size_t)(row + 8) * 128 + j) = __float22half2_rn(o1);
                    }
                }
            }
        }
    }
}

// ---------------- edge pass A (both relations): e = exp(k[src].q[dst]); s[dst] += e ----------------
__global__ void __launch_bounds__(256) edge_a_kernel(const int* __restrict__ src0,
                                                     const int* __restrict__ dst0,
                                                     const int* __restrict__ src1,
                                                     const int* __restrict__ dst1) {
    int warp = (blockIdx.x * blockDim.x + threadIdx.x) >> 5;
    int lane = threadIdx.x & 31;
    if (warp >= N_EDGES) return;
    int rel = blockIdx.y;
    const int* src = rel ? src1 : src0;
    const int* dst = rel ? dst1 : dst0;
    int sn = src[warp];
    int dn = dst[warp];
    const __half2* kr = (const __half2*)(g_K + (size_t)rel * N_NODES * 128 + (size_t)sn * 128);
    const __half2* qr = (const __half2*)(g_Q + (size_t)rel * N_NODES * 128 + (size_t)dn * 128);
    // 64 half2 per row; lane handles 2 (head0: lanes 0-15, head1: 16-31)
    __half2 a0 = kr[lane * 2], a1 = kr[lane * 2 + 1];
    __half2 b0 = qr[lane * 2], b1 = qr[lane * 2 + 1];
    float2 fa0 = __half22float2(a0), fa1 = __half22float2(a1);
    float2 fb0 = __half22float2(b0), fb1 = __half22float2(b1);
    float p = fa0.x * fb0.x + fa0.y * fb0.y + fa1.x * fb1.x + fa1.y * fb1.y;
    p += __shfl_xor_sync(0xffffffffu, p, 1);
    p += __shfl_xor_sync(0xffffffffu, p, 2);
    p += __shfl_xor_sync(0xffffffffu, p, 4);
    p += __shfl_xor_sync(0xffffffffu, p, 8);
    float el = expf(p);
    float* s = g_s + rel * (N_NODES * 2);
    float* att = g_att + (size_t)rel * N_EDGES * 2;
    if (lane == 0) {
        att[(size_t)warp * 2 + 0] = el;
        atomicAdd(&s[dn * 2 + 0], el);
    }
    if (lane == 16) {
        att[(size_t)warp * 2 + 1] = el;
        atomicAdd(&s[dn * 2 + 1], el);
    }
}

// ---------------- edge pass B (both relations): upd[dst] += v[src] * (e / s[dst]) ----------------
__global__ void __launch_bounds__(256) edge_b_kernel(const int* __restrict__ src0,
                                                     const int* __restrict__ dst0,
                                                     const int* __restrict__ src1,
                                                     const int* __restrict__ dst1) {
    int warp = (blockIdx.x * blockDim.x + threadIdx.x) >> 5;
    int lane = threadIdx.x & 31;
    if (warp >= N_EDGES) return;
    int rel = blockIdx.y;
    const int* src = rel ? src1 : src0;
    const int* dst = rel ? dst1 : dst0;
    int sn = src[warp];
    int dn = dst[warp];
    const float* s = g_s + rel * (N_NODES * 2);
    const float* att = g_att + (size_t)rel * N_EDGES * 2;
    float w0 = att[(size_t)warp * 2 + 0] / s[dn * 2 + 0];
    float w1 = att[(size_t)warp * 2 + 1] / s[dn * 2 + 1];
    float w = (lane < 16) ? w0 : w1;
    const float4* vr = (const float4*)(g_V + (size_t)rel * N_NODES * 128 + (size_t)sn * 128);
    float4 v = vr[lane];
    float* o = g_upd + (size_t)dn * DIM + lane * 4;
    atomicAdd(o + 0, v.x * w);
    atomicAdd(o + 1, v.y * w);
    atomicAdd(o + 2, v.z * w);
    atomicAdd(o + 3, v.w * w);
}

// ---------------- launch ----------------
extern "C" void kernel_launch(void* const* d_in, const int* in_sizes, int n_in,
                              void* d_out, int out_size) {
    const float* feat = (const float*)d_in[0];
    const int* src0 = (const int*)d_in[1];
    const int* dst0 = (const int*)d_in[2];
    const int* src1 = (const int*)d_in[3];
    const int* dst1 = (const int*)d_in[4];
    const float* Wk = (const float*)d_in[5];
    const float* bk = (const float*)d_in[6];
    const float* Wq = (const float*)d_in[7];
    const float* bq = (const float*)d_in[8];
    const float* Wv = (const float*)d_in[9];
    const float* bv = (const float*)d_in[10];
    const float* Wo = (const float*)d_in[11];
    const float* bo = (const float*)d_in[12];
    const float* We0 = (const float*)d_in[13];
    const float* be0 = (const float*)d_in[14];
    const float* We1 = (const float*)d_in[15];
    const float* be1 = (const float*)d_in[16];
    float* out = (float*)d_out;

    void *pbc, *pupd, *pWCh, *pWCl, *pWoh, *pWol;
    cudaGetSymbolAddress(&pbc, g_bc);
    cudaGetSymbolAddress(&pupd, g_upd);
    cudaGetSymbolAddress(&pWCh, g_WCt_hi);
    cudaGetSymbolAddress(&pWCl, g_WCt_lo);
    cudaGetSymbolAddress(&pWoh, g_Wot_hi);
    cudaGetSymbolAddress(&pWol, g_Wot_lo);

    cudaFuncSetAttribute(hgemm_kernel, cudaFuncAttributeMaxDynamicSharedMemorySize, 98304);

    zero_kernel<<<2048, 256>>>();
    prep_kernel<<<KQV_COLS, 128>>>(Wk, bk, Wq, bq, Wv, bv, We0, be0, We1, be1);
    prep_wo_kernel<<<128, 128>>>(Wo);

    const int Mtiles = (N_NODES + 63) / 64;  // 3125

    // K/Q/V = feat @ WC + bc  ([200000,128] x [128,768]), routed outputs
    hgemm_kernel<<<Mtiles, 256, 98304>>>(
        feat, (const __nv_bfloat16*)pWCh, (const __nv_bfloat16*)pWCl,
        (const float*)pbc, nullptr, KQV_COLS, N_NODES, 6, 1);

    const int eblocks = N_EDGES / 8;
    edge_a_kernel<<<dim3(eblocks, 2), 256>>>(src0, dst0, src1, dst1);
    edge_b_kernel<<<dim3(eblocks, 2), 256>>>(src0, dst0, src1, dst1);

    // out = upd @ Wo + bo  ([200000,128] x [128,128])
    hgemm_kernel<<<Mtiles, 256, 98304>>>(
        (const float*)pupd, (const __nv_bfloat16*)pWoh, (const __nv_bfloat16*)pWol,
        bo, out, DIM, N_NODES, 1, 0);
}

// round 6
// speedup vs baseline: 2.6943x; 1.1800x over previous
#include <cuda_runtime.h>
#include <cuda_fp16.h>
#include <stdint.h>
#include <math.h>

#define N_NODES 200000
#define N_EDGES 500000
#define DIM 128
#define KQV_COLS 768   // bias layout: [k0 q0 v0 | k1 q1 v1]

// ---------------- scratch (device globals; no allocation allowed) ----------------
__device__ __align__(16) float g_bc[KQV_COLS];                   // fused bias
__device__ __align__(16) __half g_WCt[KQV_COLS * 128];           // fused W^T [n][k], fp16
__device__ __align__(16) __half g_Wot[128 * 128];                // Wo^T [n][k], fp16
__device__ __align__(16) __half g_K[2 * (size_t)N_NODES * 128];  // fp16 K per rel
__device__ __align__(16) __half g_Q[2 * (size_t)N_NODES * 128];  // fp16 Q per rel (scaled)
__device__ __align__(16) float g_V[2 * (size_t)N_NODES * 128];   // fp32 V per rel
__device__ __align__(16) float g_upd[(size_t)N_NODES * DIM];
__device__ __align__(16) float g_s[2 * N_NODES * 2];             // per-rel segment sums
__device__ __align__(16) float g_att[2 * (size_t)N_EDGES * 2];   // per-rel exp(logit)

// ---------------- helpers ----------------
static __device__ __forceinline__ uint32_t smem_u32(const void* p) {
    uint32_t a;
    asm("{ .reg .u64 t; cvta.to.shared.u64 t, %1; cvt.u32.u64 %0, t; }" : "=r"(a) : "l"(p));
    return a;
}
static __device__ __forceinline__ uint32_t packh2(__half a, __half b) {
    uint16_t ua = *(uint16_t*)&a, ub = *(uint16_t*)&b;
    return (uint32_t)ua | ((uint32_t)ub << 16);
}
// fp16 big-little split of two floats
static __device__ __forceinline__ void split2h(float a, float b, uint32_t& h, uint32_t& l) {
    __half ha = __float2half_rn(a), hb = __float2half_rn(b);
    float ra = a - __half2float(ha), rb = b - __half2float(hb);
    h = packh2(ha, hb);
    l = packh2(__float2half_rn(ra), __float2half_rn(rb));
}

#define LDSM4(r, addr)                                                           \
    asm volatile("ldmatrix.sync.aligned.m8n8.x4.shared.b16 {%0,%1,%2,%3}, [%4];" \
                 : "=r"((r)[0]), "=r"((r)[1]), "=r"((r)[2]), "=r"((r)[3])        \
                 : "r"(addr))

#define MMAH(c, a, b0, b1)                                                    \
    asm volatile(                                                             \
        "mma.sync.aligned.m16n8k16.row.col.f32.f16.f16.f32 "                  \
        "{%0,%1,%2,%3},{%4,%5,%6,%7},{%8,%9},{%0,%1,%2,%3};"                  \
        : "+f"((c)[0]), "+f"((c)[1]), "+f"((c)[2]), "+f"((c)[3])              \
        : "r"((a)[0]), "r"((a)[1]), "r"((a)[2]), "r"((a)[3]), "r"(b0), "r"(b1))

#define CP_ASYNC16(dst, src) \
    asm volatile("cp.async.ca.shared.global [%0], [%1], 16;" :: "r"(dst), "l"(src))
#define CP_COMMIT() asm volatile("cp.async.commit_group;")
#define CP_WAIT0() asm volatile("cp.async.wait_group 0;")

// ---------------- zero scratch that is accumulated into ----------------
__global__ void zero_kernel() {
    size_t i0 = blockIdx.x * (size_t)blockDim.x + threadIdx.x;
    size_t stride = gridDim.x * (size_t)blockDim.x;
    float4* u = (float4*)g_upd;
    const size_t nu = (size_t)N_NODES * DIM / 4;
    for (size_t i = i0; i < nu; i += stride) u[i] = make_float4(0.f, 0.f, 0.f, 0.f);
    float4* s = (float4*)g_s;
    const size_t ns = (size_t)2 * N_NODES * 2 / 4;
    for (size_t i = i0; i < ns; i += stride) s[i] = make_float4(0.f, 0.f, 0.f, 0.f);
}

// ---------------- fold node-type + edge-type linears; emit fp16 transposed ----------------
__global__ void prep_kernel(const float* __restrict__ Wk, const float* __restrict__ bk,
                            const float* __restrict__ Wq, const float* __restrict__ bq,
                            const float* __restrict__ Wv, const float* __restrict__ bv,
                            const float* __restrict__ We0, const float* __restrict__ be0,
                            const float* __restrict__ We1, const float* __restrict__ be1) {
    int c = blockIdx.x;           // 0..767
    int i = threadIdx.x;          // 0..127  (k index)
    int r = c / 384;
    int rem = c % 384;
    int t = rem / 128;
    int j = rem % 128;
    const float* We = r ? We1 : We0;
    const float* be = r ? be1 : be0;
    const float* Wt = (t == 0) ? Wk : (t == 1) ? Wq : Wv;
    const float* bt = (t == 0) ? bk : (t == 1) ? bq : bv;
    const float scale = (t == 1) ? 0.125f : 1.0f;

    __shared__ float sWe[128];
    sWe[i] = We[i * 128 + j];
    __syncthreads();

    float acc = 0.f;
#pragma unroll 8
    for (int m = 0; m < 128; m++) acc += Wt[i * 128 + m] * sWe[m];
    g_WCt[c * 128 + i] = __float2half_rn(acc * scale);

    if (i == 0) {
        float b = 0.f;
        for (int m = 0; m < 128; m++) b += bt[m] * sWe[m];
        g_bc[c] = (b + be[j]) * scale;
    }
}

__global__ void prep_wo_kernel(const float* __restrict__ Wo) {
    int n = blockIdx.x;   // 0..127
    int i = threadIdx.x;  // 0..127 (k index)
    g_Wot[n * 128 + i] = __float2half_rn(Wo[i * 128 + n]);
}

// ---------------- HMMA GEMM: [Mrows,128] x [128, NTILES*128] + bias ----------------
// fp16 2-pass big-little: C = Ah*Bh + Al*Bh (A full precision vs fp16-rounded B).
// CTA: 256 threads (8 warps), 128 rows; warp tile 32m x 64n. smem 96KB -> 2 CTAs/SM.
// smem: AH 32K @0 | AL 32K @32768 | BH 32K @65536. Swizzle: 256B rows, chunk^(row&7).
// route=0: fp32 C (stride COLS). route=1: per-tile KQV routing (K,Q fp16; V fp32).
__global__ void __launch_bounds__(256) hgemm_kernel(
    const float* __restrict__ A,
    const __half* __restrict__ Bt,
    const float* __restrict__ bias,
    float* __restrict__ C,
    int COLS, int Mrows, int NTILES, int route) {
    extern __shared__ char smem[];
    const uint32_t sb = smem_u32(smem);
    const int tid = threadIdx.x;
    const int m0 = blockIdx.x * 128;
    const int SM_AL = 32768, SM_BH = 65536;

    auto loadB = [&](int n0) {
#pragma unroll
        for (int it = 0; it < 8; it++) {
            int u = tid + it * 256;          // 0..2047
            int row = u >> 4, kb = u & 15;
            uint32_t off = row * 256 + ((uint32_t)(kb ^ (row & 7)) << 4);
            const char* gh = (const char*)(Bt + (size_t)(n0 + row) * 128) + kb * 16;
            CP_ASYNC16(sb + SM_BH + off, gh);
        }
        CP_COMMIT();
    };
    loadB(0);

    // A tile: 128 rows, fp32 -> fp16 hi/lo, swizzled
#pragma unroll
    for (int it = 0; it < 8; it++) {
        int u = tid + it * 256;              // 0..2047
        int row = u >> 4, kb = u & 15;
        int gr = m0 + row;
        float4 v0 = make_float4(0.f, 0.f, 0.f, 0.f), v1 = v0;
        if (gr < Mrows) {
            const float* p = A + (size_t)gr * 128 + kb * 8;
            v0 = *(const float4*)p;
            v1 = *(const float4*)(p + 4);
        }
        uint32_t h[4], l[4];
        split2h(v0.x, v0.y, h[0], l[0]);
        split2h(v0.z, v0.w, h[1], l[1]);
        split2h(v1.x, v1.y, h[2], l[2]);
        split2h(v1.z, v1.w, h[3], l[3]);
        uint32_t off = row * 256 + ((uint32_t)(kb ^ (row & 7)) << 4);
        *(uint4*)(smem + off) = make_uint4(h[0], h[1], h[2], h[3]);
        *(uint4*)(smem + SM_AL + off) = make_uint4(l[0], l[1], l[2], l[3]);
    }

    // 8 warps -> 4m x 2n grid of 32m x 64n warp tiles
    const int wid = tid >> 5, lane = tid & 31;
    const int wm = wid & 3, wn = wid >> 2;
    const uint32_t x7 = lane & 7;
    const uint32_t aRow = wm * 32 + (lane & 15);
    const uint32_t akoff = lane >> 4;
    const uint32_t bRow = wn * 64 + (lane & 7) + ((lane >> 4) << 3);
    const uint32_t bkoff = (lane >> 3) & 1;
    const uint32_t ah_base = sb + aRow * 256;
    const uint32_t al_base = sb + SM_AL + aRow * 256;
    const uint32_t bh_base = sb + SM_BH + bRow * 256;
    const int g = lane >> 2, tg = lane & 3;

    for (int nt = 0; nt < NTILES; nt++) {
        CP_WAIT0();
        __syncthreads();

        float acc[2][8][4] = {};
#pragma unroll
        for (int kc = 0; kc < 8; kc++) {
            const uint32_t kxa = (((2 * kc + akoff) ^ x7) << 4);
            const uint32_t kxb = (((2 * kc + bkoff) ^ x7) << 4);
            uint32_t AH[2][4], AL[2][4], BH[4][4];
#pragma unroll
            for (int ma = 0; ma < 2; ma++) LDSM4(AH[ma], ah_base + ma * 4096 + kxa);
#pragma unroll
            for (int nb = 0; nb < 4; nb++) LDSM4(BH[nb], bh_base + nb * 4096 + kxb);
#pragma unroll
            for (int ma = 0; ma < 2; ma++) LDSM4(AL[ma], al_base + ma * 4096 + kxa);
#pragma unroll
            for (int ma = 0; ma < 2; ma++)
#pragma unroll
                for (int nb = 0; nb < 4; nb++) {
                    MMAH(acc[ma][nb * 2 + 0], AH[ma], BH[nb][0], BH[nb][1]);
                    MMAH(acc[ma][nb * 2 + 1], AH[ma], BH[nb][2], BH[nb][3]);
                }
#pragma unroll
            for (int ma = 0; ma < 2; ma++)
#pragma unroll
                for (int nb = 0; nb < 4; nb++) {
                    MMAH(acc[ma][nb * 2 + 0], AL[ma], BH[nb][0], BH[nb][1]);
                    MMAH(acc[ma][nb * 2 + 1], AL[ma], BH[nb][2], BH[nb][3]);
                }
        }

        // prefetch next B after all warps finished reading this one
        __syncthreads();
        if (nt + 1 < NTILES) loadB((nt + 1) * 128);

        // ---- epilogue ----
        if (route == 0) {
#pragma unroll
            for (int ma = 0; ma < 2; ma++) {
                int row = m0 + wm * 32 + ma * 16 + g;
#pragma unroll
                for (int x = 0; x < 8; x++) {
                    int col = nt * 128 + wn * 64 + x * 8 + tg * 2;
                    float2 bb = *(const float2*)(bias + col);
                    float* c = acc[ma][x];
                    if (row < Mrows)
                        *(float2*)(C + (size_t)row * COLS + col) =
                            make_float2(c[0] + bb.x, c[1] + bb.y);
                    if (row + 8 < Mrows)
                        *(float2*)(C + (size_t)(row + 8) * COLS + col) =
                            make_float2(c[2] + bb.x, c[3] + bb.y);
                }
            }
        } else {
            int r = nt / 3, t = nt - r * 3;
            float* vout = g_V + (size_t)r * N_NODES * 128;
            __half* hout = (t == 0 ? g_K : g_Q) + (size_t)r * N_NODES * 128;
#pragma unroll
            for (int ma = 0; ma < 2; ma++) {
                int row = m0 + wm * 32 + ma * 16 + g;
#pragma unroll
                for (int x = 0; x < 8; x++) {
                    int j = wn * 64 + x * 8 + tg * 2;
                    float2 bb = *(const float2*)(bias + nt * 128 + j);
                    float* c = acc[ma][x];
                    float2 o0 = make_float2(c[0] + bb.x, c[1] + bb.y);
                    float2 o1 = make_float2(c[2] + bb.x, c[3] + bb.y);
                    if (t == 2) {
                        if (row < Mrows) *(float2*)(vout + (size_t)row * 128 + j) = o0;
                        if (row + 8 < Mrows) *(float2*)(vout + (size_t)(row + 8) * 128 + j) = o1;
                    } else {
                        if (row < Mrows)
                            *(__half2*)(hout + (size_t)row * 128 + j) = __float22half2_rn(o0);
                        if (row + 8 < Mrows)
                            *(__half2*)(hout + (size_t)(row + 8) * 128 + j) = __float22half2_rn(o1);
                    }
                }
            }
        }
    }
}

// ---------------- edge pass A (both relations): e = exp(k[src].q[dst]); s[dst] += e ----------------
__global__ void __launch_bounds__(256) edge_a_kernel(const int* __restrict__ src0,
                                                     const int* __restrict__ dst0,
                                                     const int* __restrict__ src1,
                                                     const int* __restrict__ dst1) {
    int warp = (blockIdx.x * blockDim.x + threadIdx.x) >> 5;
    int lane = threadIdx.x & 31;
    if (warp >= N_EDGES) return;
    int rel = blockIdx.y;
    const int* src = rel ? src1 : src0;
    const int* dst = rel ? dst1 : dst0;
    int sn = src[warp];
    int dn = dst[warp];
    const __half2* kr = (const __half2*)(g_K + (size_t)rel * N_NODES * 128 + (size_t)sn * 128);
    const __half2* qr = (const __half2*)(g_Q + (size_t)rel * N_NODES * 128 + (size_t)dn * 128);
    __half2 a0 = kr[lane * 2], a1 = kr[lane * 2 + 1];
    __half2 b0 = qr[lane * 2], b1 = qr[lane * 2 + 1];
    float2 fa0 = __half22float2(a0), fa1 = __half22float2(a1);
    float2 fb0 = __half22float2(b0), fb1 = __half22float2(b1);
    float p = fa0.x * fb0.x + fa0.y * fb0.y + fa1.x * fb1.x + fa1.y * fb1.y;
    p += __shfl_xor_sync(0xffffffffu, p, 1);
    p += __shfl_xor_sync(0xffffffffu, p, 2);
    p += __shfl_xor_sync(0xffffffffu, p, 4);
    p += __shfl_xor_sync(0xffffffffu, p, 8);
    float el = expf(p);
    float* s = g_s + rel * (N_NODES * 2);
    float* att = g_att + (size_t)rel * N_EDGES * 2;
    if (lane == 0) {
        att[(size_t)warp * 2 + 0] = el;
        atomicAdd(&s[dn * 2 + 0], el);
    }
    if (lane == 16) {
        att[(size_t)warp * 2 + 1] = el;
        atomicAdd(&s[dn * 2 + 1], el);
    }
}

// ---------------- edge pass B (both relations): upd[dst] += v[src] * (e / s[dst]) ----------------
__global__ void __launch_bounds__(256) edge_b_kernel(const int* __restrict__ src0,
                                                     const int* __restrict__ dst0,
                                                     const int* __restrict__ src1,
                                                     const int* __restrict__ dst1) {
    int warp = (blockIdx.x * blockDim.x + threadIdx.x) >> 5;
    int lane = threadIdx.x & 31;
    if (warp >= N_EDGES) return;
    int rel = blockIdx.y;
    const int* src = rel ? src1 : src0;
    const int* dst = rel ? dst1 : dst0;
    int sn = src[warp];
    int dn = dst[warp];
    const float* s = g_s + rel * (N_NODES * 2);
    const float* att = g_att + (size_t)rel * N_EDGES * 2;
    float w0 = att[(size_t)warp * 2 + 0] / s[dn * 2 + 0];
    float w1 = att[(size_t)warp * 2 + 1] / s[dn * 2 + 1];
    float w = (lane < 16) ? w0 : w1;
    const float4* vr = (const float4*)(g_V + (size_t)rel * N_NODES * 128 + (size_t)sn * 128);
    float4 v = vr[lane];
    float* o = g_upd + (size_t)dn * DIM + lane * 4;
    // one 16B vector reduction instead of 4 scalar atomics
    asm volatile("red.global.add.v4.f32 [%0], {%1, %2, %3, %4};"
                 :: "l"(o), "f"(v.x * w), "f"(v.y * w), "f"(v.z * w), "f"(v.w * w)
                 : "memory");
}

// ---------------- launch ----------------
extern "C" void kernel_launch(void* const* d_in, const int* in_sizes, int n_in,
                              void* d_out, int out_size) {
    const float* feat = (const float*)d_in[0];
    const int* src0 = (const int*)d_in[1];
    const int* dst0 = (const int*)d_in[2];
    const int* src1 = (const int*)d_in[3];
    const int* dst1 = (const int*)d_in[4];
    const float* Wk = (const float*)d_in[5];
    const float* bk = (const float*)d_in[6];
    const float* Wq = (const float*)d_in[7];
    const float* bq = (const float*)d_in[8];
    const float* Wv = (const float*)d_in[9];
    const float* bv = (const float*)d_in[10];
    const float* Wo = (const float*)d_in[11];
    const float* bo = (const float*)d_in[12];
    const float* We0 = (const float*)d_in[13];
    const float* be0 = (const float*)d_in[14];
    const float* We1 = (const float*)d_in[15];
    const float* be1 = (const float*)d_in[16];
    float* out = (float*)d_out;

    void *pbc, *pupd, *pWC, *pWo;
    cudaGetSymbolAddress(&pbc, g_bc);
    cudaGetSymbolAddress(&pupd, g_upd);
    cudaGetSymbolAddress(&pWC, g_WCt);
    cudaGetSymbolAddress(&pWo, g_Wot);

    cudaFuncSetAttribute(hgemm_kernel, cudaFuncAttributeMaxDynamicSharedMemorySize, 98304);

    zero_kernel<<<2048, 256>>>();
    prep_kernel<<<KQV_COLS, 128>>>(Wk, bk, Wq, bq, Wv, bv, We0, be0, We1, be1);
    prep_wo_kernel<<<128, 128>>>(Wo);

    const int Mtiles = (N_NODES + 127) / 128;  // 1563

    // K/Q/V = feat @ WC + bc  ([200000,128] x [128,768]), routed outputs
    hgemm_kernel<<<Mtiles, 256, 98304>>>(
        feat, (const __half*)pWC, (const float*)pbc, nullptr, KQV_COLS, N_NODES, 6, 1);

    const int eblocks = N_EDGES / 8;
    edge_a_kernel<<<dim3(eblocks, 2), 256>>>(src0, dst0, src1, dst1);
    edge_b_kernel<<<dim3(eblocks, 2), 256>>>(src0, dst0, src1, dst1);

    // out = upd @ Wo + bo  ([200000,128] x [128,128])
    hgemm_kernel<<<Mtiles, 256, 98304>>>(
        (const float*)pupd, (const __half*)pWo, bo, out, DIM, N_NODES, 1, 0);
}

// round 7
// speedup vs baseline: 3.1776x; 1.1793x over previous
#include <cuda_runtime.h>
#include <cuda_fp16.h>
#include <stdint.h>
#include <math.h>

#define N_NODES 200000
#define N_EDGES 500000
#define DIM 128
#define KQV_COLS 768   // bias layout: [k0 q0 v0 | k1 q1 v1]

// ---------------- scratch (device globals; no allocation allowed) ----------------
__device__ __align__(16) float g_bc[KQV_COLS];                   // fused bias
__device__ __align__(16) __half g_WCt[KQV_COLS * 128];           // fused W^T [n][k], fp16
__device__ __align__(16) __half g_Wot[128 * 128];                // Wo^T [n][k], fp16
__device__ __align__(16) __half g_K[2 * (size_t)N_NODES * 128];  // fp16 K per rel
__device__ __align__(16) __half g_Q[2 * (size_t)N_NODES * 128];  // fp16 Q per rel (scaled)
__device__ __align__(16) __half g_V[2 * (size_t)N_NODES * 128];  // fp16 V per rel
__device__ __align__(16) float g_upd0[(size_t)N_NODES * DIM];    // raw (unnormalized) rel0
__device__ __align__(16) float g_upd1[(size_t)N_NODES * DIM];    // raw (unnormalized) rel1
__device__ __align__(16) float g_s[2 * N_NODES * 2];             // per-rel segment sums [rel][node][head]

// ---------------- helpers ----------------
static __device__ __forceinline__ uint32_t smem_u32(const void* p) {
    uint32_t a;
    asm("{ .reg .u64 t; cvta.to.shared.u64 t, %1; cvt.u32.u64 %0, t; }" : "=r"(a) : "l"(p));
    return a;
}
static __device__ __forceinline__ uint32_t packh2(__half a, __half b) {
    uint16_t ua = *(uint16_t*)&a, ub = *(uint16_t*)&b;
    return (uint32_t)ua | ((uint32_t)ub << 16);
}
// fp16 big-little split of two floats
static __device__ __forceinline__ void split2h(float a, float b, uint32_t& h, uint32_t& l) {
    __half ha = __float2half_rn(a), hb = __float2half_rn(b);
    float ra = a - __half2float(ha), rb = b - __half2float(hb);
    h = packh2(ha, hb);
    l = packh2(__float2half_rn(ra), __float2half_rn(rb));
}

#define LDSM4(r, addr)                                                           \
    asm volatile("ldmatrix.sync.aligned.m8n8.x4.shared.b16 {%0,%1,%2,%3}, [%4];" \
                 : "=r"((r)[0]), "=r"((r)[1]), "=r"((r)[2]), "=r"((r)[3])        \
                 : "r"(addr))

#define MMAH(c, a, b0, b1)                                                    \
    asm volatile(                                                             \
        "mma.sync.aligned.m16n8k16.row.col.f32.f16.f16.f32 "                  \
        "{%0,%1,%2,%3},{%4,%5,%6,%7},{%8,%9},{%0,%1,%2,%3};"                  \
        : "+f"((c)[0]), "+f"((c)[1]), "+f"((c)[2]), "+f"((c)[3])              \
        : "r"((a)[0]), "r"((a)[1]), "r"((a)[2]), "r"((a)[3]), "r"(b0), "r"(b1))

#define CP_ASYNC16(dst, src) \
    asm volatile("cp.async.ca.shared.global [%0], [%1], 16;" :: "r"(dst), "l"(src))
#define CP_COMMIT() asm volatile("cp.async.commit_group;")
#define CP_WAIT0() asm volatile("cp.async.wait_group 0;")

// ---------------- zero scratch that is accumulated into ----------------
__global__ void zero_kernel() {
    size_t i0 = blockIdx.x * (size_t)blockDim.x + threadIdx.x;
    size_t stride = gridDim.x * (size_t)blockDim.x;
    const size_t nu = (size_t)N_NODES * DIM / 4;
    float4* u0 = (float4*)g_upd0;
    float4* u1 = (float4*)g_upd1;
    for (size_t i = i0; i < nu; i += stride) {
        u0[i] = make_float4(0.f, 0.f, 0.f, 0.f);
        u1[i] = make_float4(0.f, 0.f, 0.f, 0.f);
    }
    float4* s = (float4*)g_s;
    const size_t ns = (size_t)2 * N_NODES * 2 / 4;
    for (size_t i = i0; i < ns; i += stride) s[i] = make_float4(0.f, 0.f, 0.f, 0.f);
}

// ---------------- fold node-type + edge-type linears; emit fp16 transposed ----------------
__global__ void prep_kernel(const float* __restrict__ Wk, const float* __restrict__ bk,
                            const float* __restrict__ Wq, const float* __restrict__ bq,
                            const float* __restrict__ Wv, const float* __restrict__ bv,
                            const float* __restrict__ We0, const float* __restrict__ be0,
                            const float* __restrict__ We1, const float* __restrict__ be1) {
    int c = blockIdx.x;           // 0..767
    int i = threadIdx.x;          // 0..127  (k index)
    int r = c / 384;
    int rem = c % 384;
    int t = rem / 128;
    int j = rem % 128;
    const float* We = r ? We1 : We0;
    const float* be = r ? be1 : be0;
    const float* Wt = (t == 0) ? Wk : (t == 1) ? Wq : Wv;
    const float* bt = (t == 0) ? bk : (t == 1) ? bq : bv;
    const float scale = (t == 1) ? 0.125f : 1.0f;

    __shared__ float sWe[128];
    sWe[i] = We[i * 128 + j];
    __syncthreads();

    float acc = 0.f;
#pragma unroll 8
    for (int m = 0; m < 128; m++) acc += Wt[i * 128 + m] * sWe[m];
    g_WCt[c * 128 + i] = __float2half_rn(acc * scale);

    if (i == 0) {
        float b = 0.f;
        for (int m = 0; m < 128; m++) b += bt[m] * sWe[m];
        g_bc[c] = (b + be[j]) * scale;
    }
}

__global__ void prep_wo_kernel(const float* __restrict__ Wo) {
    int n = blockIdx.x;   // 0..127
    int i = threadIdx.x;  // 0..127 (k index)
    g_Wot[n * 128 + i] = __float2half_rn(Wo[i * 128 + n]);
}

// ---------------- HMMA GEMM: [Mrows,128] x [128, NTILES*128] + bias ----------------
// fp16 2-pass big-little: C = Ah*Bh + Al*Bh. CTA: 256 threads, 128 rows, warp 32x64.
// smem 96KB (AH|AL|BH), forced 2 CTAs/SM via launch_bounds.
// route=0: fp32 C+bias.  route=1: per-tile KQV fp16 routing.
// scaled!=0: A-load combines g_upd0/g_upd1 with per-(row,head) 1/s normalization.
__global__ void __launch_bounds__(256, 2) hgemm_kernel(
    const float* __restrict__ A,
    const __half* __restrict__ Bt,
    const float* __restrict__ bias,
    float* __restrict__ C,
    int COLS, int Mrows, int NTILES, int route, int scaled) {
    extern __shared__ char smem[];
    const uint32_t sb = smem_u32(smem);
    const int tid = threadIdx.x;
    const int m0 = blockIdx.x * 128;
    const int SM_AL = 32768, SM_BH = 65536;

    auto loadB = [&](int n0) {
#pragma unroll
        for (int it = 0; it < 8; it++) {
            int u = tid + it * 256;          // 0..2047
            int row = u >> 4, kb = u & 15;
            uint32_t off = row * 256 + ((uint32_t)(kb ^ (row & 7)) << 4);
            const char* gh = (const char*)(Bt + (size_t)(n0 + row) * 128) + kb * 16;
            CP_ASYNC16(sb + SM_BH + off, gh);
        }
        CP_COMMIT();
    };
    loadB(0);

    // A tile: 128 rows, fp32 -> fp16 hi/lo, swizzled
#pragma unroll
    for (int it = 0; it < 8; it++) {
        int u = tid + it * 256;              // 0..2047
        int row = u >> 4, kb = u & 15;
        int gr = m0 + row;
        float4 v0 = make_float4(0.f, 0.f, 0.f, 0.f), v1 = v0;
        if (gr < Mrows) {
            if (!scaled) {
                const float* p = A + (size_t)gr * 128 + kb * 8;
                v0 = *(const float4*)p;
                v1 = *(const float4*)(p + 4);
            } else {
                int h = kb >> 3;   // cols kb*8..kb*8+7 all in head h
                float s0 = g_s[0 * (N_NODES * 2) + gr * 2 + h];
                float s1 = g_s[1 * (N_NODES * 2) + gr * 2 + h];
                float inv0 = (s0 != 0.f) ? 1.f / s0 : 0.f;
                float inv1 = (s1 != 0.f) ? 1.f / s1 : 0.f;
                const float* p0 = g_upd0 + (size_t)gr * 128 + kb * 8;
                const float* p1 = g_upd1 + (size_t)gr * 128 + kb * 8;
                float4 a0 = *(const float4*)p0, a1 = *(const float4*)(p0 + 4);
                float4 b0 = *(const float4*)p1, b1 = *(const float4*)(p1 + 4);
                v0 = make_float4(a0.x * inv0 + b0.x * inv1, a0.y * inv0 + b0.y * inv1,
                                 a0.z * inv0 + b0.z * inv1, a0.w * inv0 + b0.w * inv1);
                v1 = make_float4(a1.x * inv0 + b1.x * inv1, a1.y * inv0 + b1.y * inv1,
                                 a1.z * inv0 + b1.z * inv1, a1.w * inv0 + b1.w * inv1);
            }
        }
        uint32_t h[4], l[4];
        split2h(v0.x, v0.y, h[0], l[0]);
        split2h(v0.z, v0.w, h[1], l[1]);
        split2h(v1.x, v1.y, h[2], l[2]);
        split2h(v1.z, v1.w, h[3], l[3]);
        uint32_t off = row * 256 + ((uint32_t)(kb ^ (row & 7)) << 4);
        *(uint4*)(smem + off) = make_uint4(h[0], h[1], h[2], h[3]);
        *(uint4*)(smem + SM_AL + off) = make_uint4(l[0], l[1], l[2], l[3]);
    }

    // 8 warps -> 4m x 2n grid of 32m x 64n warp tiles
    const int wid = tid >> 5, lane = tid & 31;
    const int wm = wid & 3, wn = wid >> 2;
    const uint32_t x7 = lane & 7;
    const uint32_t aRow = wm * 32 + (lane & 15);
    const uint32_t akoff = lane >> 4;
    const uint32_t bRow = wn * 64 + (lane & 7) + ((lane >> 4) << 3);
    const uint32_t bkoff = (lane >> 3) & 1;
    const uint32_t ah_base = sb + aRow * 256;
    const uint32_t al_base = sb + SM_AL + aRow * 256;
    const uint32_t bh_base = sb + SM_BH + bRow * 256;
    const int g = lane >> 2, tg = lane & 3;

    for (int nt = 0; nt < NTILES; nt++) {
        CP_WAIT0();
        __syncthreads();

        float acc[2][8][4] = {};
#pragma unroll
        for (int kc = 0; kc < 8; kc++) {
            const uint32_t kxa = (((2 * kc + akoff) ^ x7) << 4);
            const uint32_t kxb = (((2 * kc + bkoff) ^ x7) << 4);
            uint32_t AH[2][4], AL[2][4], BH[4][4];
#pragma unroll
            for (int ma = 0; ma < 2; ma++) LDSM4(AH[ma], ah_base + ma * 4096 + kxa);
#pragma unroll
            for (int nb = 0; nb < 4; nb++) LDSM4(BH[nb], bh_base + nb * 4096 + kxb);
#pragma unroll
            for (int ma = 0; ma < 2; ma++) LDSM4(AL[ma], al_base + ma * 4096 + kxa);
#pragma unroll
            for (int ma = 0; ma < 2; ma++)
#pragma unroll
                for (int nb = 0; nb < 4; nb++) {
                    MMAH(acc[ma][nb * 2 + 0], AH[ma], BH[nb][0], BH[nb][1]);
                    MMAH(acc[ma][nb * 2 + 1], AH[ma], BH[nb][2], BH[nb][3]);
                }
#pragma unroll
            for (int ma = 0; ma < 2; ma++)
#pragma unroll
                for (int nb = 0; nb < 4; nb++) {
                    MMAH(acc[ma][nb * 2 + 0], AL[ma], BH[nb][0], BH[nb][1]);
                    MMAH(acc[ma][nb * 2 + 1], AL[ma], BH[nb][2], BH[nb][3]);
                }
        }

        // prefetch next B after all warps finished reading this one
        __syncthreads();
        if (nt + 1 < NTILES) loadB((nt + 1) * 128);

        // ---- epilogue ----
        if (route == 0) {
#pragma unroll
            for (int ma = 0; ma < 2; ma++) {
                int row = m0 + wm * 32 + ma * 16 + g;
#pragma unroll
                for (int x = 0; x < 8; x++) {
                    int col = nt * 128 + wn * 64 + x * 8 + tg * 2;
                    float2 bb = *(const float2*)(bias + col);
                    float* c = acc[ma][x];
                    if (row < Mrows)
                        *(float2*)(C + (size_t)row * COLS + col) =
                            make_float2(c[0] + bb.x, c[1] + bb.y);
                    if (row + 8 < Mrows)
                        *(float2*)(C + (size_t)(row + 8) * COLS + col) =
                            make_float2(c[2] + bb.x, c[3] + bb.y);
                }
            }
        } else {
            int r = nt / 3, t = nt - r * 3;
            __half* hout = (t == 0 ? g_K : t == 1 ? g_Q : g_V) + (size_t)r * N_NODES * 128;
#pragma unroll
            for (int ma = 0; ma < 2; ma++) {
                int row = m0 + wm * 32 + ma * 16 + g;
#pragma unroll
                for (int x = 0; x < 8; x++) {
                    int j = wn * 64 + x * 8 + tg * 2;
                    float2 bb = *(const float2*)(bias + nt * 128 + j);
                    float* c = acc[ma][x];
                    if (row < Mrows)
                        *(__half2*)(hout + (size_t)row * 128 + j) =
                            __float22half2_rn(make_float2(c[0] + bb.x, c[1] + bb.y));
                    if (row + 8 < Mrows)
                        *(__half2*)(hout + (size_t)(row + 8) * 128 + j) =
                            __float22half2_rn(make_float2(c[2] + bb.x, c[3] + bb.y));
                }
            }
        }
    }
}

// ---------------- fused edge pass: e = exp(k[src].q[dst]); s[dst]+=e; upd_raw[dst]+=v[src]*e ----
__global__ void __launch_bounds__(256) edge_kernel(const int* __restrict__ src0,
                                                   const int* __restrict__ dst0,
                                                   const int* __restrict__ src1,
                                                   const int* __restrict__ dst1) {
    int warp = (blockIdx.x * blockDim.x + threadIdx.x) >> 5;
    int lane = threadIdx.x & 31;
    if (warp >= N_EDGES) return;
    int rel = blockIdx.y;
    const int* src = rel ? src1 : src0;
    const int* dst = rel ? dst1 : dst0;
    int sn = src[warp];
    int dn = dst[warp];
    const __half2* kr = (const __half2*)(g_K + (size_t)rel * N_NODES * 128 + (size_t)sn * 128);
    const __half2* qr = (const __half2*)(g_Q + (size_t)rel * N_NODES * 128 + (size_t)dn * 128);
    __half2 a0 = kr[lane * 2], a1 = kr[lane * 2 + 1];
    __half2 b0 = qr[lane * 2], b1 = qr[lane * 2 + 1];
    float2 fa0 = __half22float2(a0), fa1 = __half22float2(a1);
    float2 fb0 = __half22float2(b0), fb1 = __half22float2(b1);
    float p = fa0.x * fb0.x + fa0.y * fb0.y + fa1.x * fb1.x + fa1.y * fb1.y;
    // reduce within each 16-lane half (head 0 = lanes 0-15, head 1 = 16-31)
    p += __shfl_xor_sync(0xffffffffu, p, 1);
    p += __shfl_xor_sync(0xffffffffu, p, 2);
    p += __shfl_xor_sync(0xffffffffu, p, 4);
    p += __shfl_xor_sync(0xffffffffu, p, 8);
    float el = expf(p);
    float* s = g_s + rel * (N_NODES * 2);
    if (lane == 0) atomicAdd(&s[dn * 2 + 0], el);
    if (lane == 16) atomicAdd(&s[dn * 2 + 1], el);
    // unnormalized message accumulate
    const __half2* vr = (const __half2*)(g_V + (size_t)rel * N_NODES * 128 + (size_t)sn * 128);
    __half2 v0 = vr[lane * 2], v1 = vr[lane * 2 + 1];
    float2 f0 = __half22float2(v0), f1 = __half22float2(v1);
    float* o = (rel ? g_upd1 : g_upd0) + (size_t)dn * DIM + lane * 4;
    asm volatile("red.global.add.v4.f32 [%0], {%1, %2, %3, %4};"
                 :: "l"(o), "f"(f0.x * el), "f"(f0.y * el), "f"(f1.x * el), "f"(f1.y * el)
                 : "memory");
}

// ---------------- launch ----------------
extern "C" void kernel_launch(void* const* d_in, const int* in_sizes, int n_in,
                              void* d_out, int out_size) {
    const float* feat = (const float*)d_in[0];
    const int* src0 = (const int*)d_in[1];
    const int* dst0 = (const int*)d_in[2];
    const int* src1 = (const int*)d_in[3];
    const int* dst1 = (const int*)d_in[4];
    const float* Wk = (const float*)d_in[5];
    const float* bk = (const float*)d_in[6];
    const float* Wq = (const float*)d_in[7];
    const float* bq = (const float*)d_in[8];
    const float* Wv = (const float*)d_in[9];
    const float* bv = (const float*)d_in[10];
    const float* Wo = (const float*)d_in[11];
    const float* bo = (const float*)d_in[12];
    const float* We0 = (const float*)d_in[13];
    const float* be0 = (const float*)d_in[14];
    const float* We1 = (const float*)d_in[15];
    const float* be1 = (const float*)d_in[16];
    float* out = (float*)d_out;

    void *pbc, *pWC, *pWo, *pU0;
    cudaGetSymbolAddress(&pbc, g_bc);
    cudaGetSymbolAddress(&pWC, g_WCt);
    cudaGetSymbolAddress(&pWo, g_Wot);
    cudaGetSymbolAddress(&pU0, g_upd0);

    cudaFuncSetAttribute(hgemm_kernel, cudaFuncAttributeMaxDynamicSharedMemorySize, 98304);

    zero_kernel<<<2048, 256>>>();
    prep_kernel<<<KQV_COLS, 128>>>(Wk, bk, Wq, bq, Wv, bv, We0, be0, We1, be1);
    prep_wo_kernel<<<128, 128>>>(Wo);

    const int Mtiles = (N_NODES + 127) / 128;  // 1563

    // K/Q/V = feat @ WC + bc  ([200000,128] x [128,768]), routed fp16 outputs
    hgemm_kernel<<<Mtiles, 256, 98304>>>(
        feat, (const __half*)pWC, (const float*)pbc, nullptr, KQV_COLS, N_NODES, 6, 1, 0);

    const int eblocks = N_EDGES / 8;
    edge_kernel<<<dim3(eblocks, 2), 256>>>(src0, dst0, src1, dst1);

    // out = (upd0/s0 + upd1/s1) @ Wo + bo  ([200000,128] x [128,128])
    hgemm_kernel<<<Mtiles, 256, 98304>>>(
        (const float*)pU0, (const __half*)pWo, bo, out, DIM, N_NODES, 1, 0, 1);
}

// round 8
// speedup vs baseline: 4.1134x; 1.2945x over previous
#include <cuda_runtime.h>
#include <cuda_fp16.h>
#include <stdint.h>
#include <math.h>

#define N_NODES 200000
#define N_EDGES 500000
#define DIM 128
#define KQV_COLS 768   // bias layout: [k0 q0 v0 | k1 q1 v1]
#define NBUCK (2 * N_NODES)
#define SCAN_NB ((NBUCK + 2047) / 2048)   // 196

// ---------------- scratch (device globals; no allocation allowed) ----------------
__device__ __align__(16) float g_bc[KQV_COLS];                   // fused bias
__device__ __align__(16) __half g_WCt[KQV_COLS * 128];           // fused W^T [n][k], fp16
__device__ __align__(16) __half g_Wot[128 * 128];                // Wo^T [n][k], fp16
__device__ __align__(16) __half g_K[2 * (size_t)N_NODES * 128];  // fp16 K per rel
__device__ __align__(16) __half g_Q[2 * (size_t)N_NODES * 128];  // fp16 Q per rel (scaled)
__device__ __align__(16) __half g_V[2 * (size_t)N_NODES * 128];  // fp16 V per rel
__device__ __align__(16) float g_upd0[(size_t)N_NODES * DIM];    // normalized per-rel update
__device__ __align__(16) float g_upd1[(size_t)N_NODES * DIM];
// CSR build
__device__ int g_cnt[NBUCK];
__device__ int g_head[NBUCK];
__device__ int g_off[NBUCK + 1];
__device__ int g_bsum[256];
__device__ int g_boff[256];
__device__ int g_esrc[2 * N_EDGES];

// ---------------- helpers ----------------
static __device__ __forceinline__ uint32_t smem_u32(const void* p) {
    uint32_t a;
    asm("{ .reg .u64 t; cvta.to.shared.u64 t, %1; cvt.u32.u64 %0, t; }" : "=r"(a) : "l"(p));
    return a;
}
static __device__ __forceinline__ uint32_t packh2(__half a, __half b) {
    uint16_t ua = *(uint16_t*)&a, ub = *(uint16_t*)&b;
    return (uint32_t)ua | ((uint32_t)ub << 16);
}
static __device__ __forceinline__ void split2h(float a, float b, uint32_t& h, uint32_t& l) {
    __half ha = __float2half_rn(a), hb = __float2half_rn(b);
    float ra = a - __half2float(ha), rb = b - __half2float(hb);
    h = packh2(ha, hb);
    l = packh2(__float2half_rn(ra), __float2half_rn(rb));
}

#define LDSM4(r, addr)                                                           \
    asm volatile("ldmatrix.sync.aligned.m8n8.x4.shared.b16 {%0,%1,%2,%3}, [%4];" \
                 : "=r"((r)[0]), "=r"((r)[1]), "=r"((r)[2]), "=r"((r)[3])        \
                 : "r"(addr))

#define MMAH(c, a, b0, b1)                                                    \
    asm volatile(                                                             \
        "mma.sync.aligned.m16n8k16.row.col.f32.f16.f16.f32 "                  \
        "{%0,%1,%2,%3},{%4,%5,%6,%7},{%8,%9},{%0,%1,%2,%3};"                  \
        : "+f"((c)[0]), "+f"((c)[1]), "+f"((c)[2]), "+f"((c)[3])              \
        : "r"((a)[0]), "r"((a)[1]), "r"((a)[2]), "r"((a)[3]), "r"(b0), "r"(b1))

#define CP_ASYNC16(dst, src) \
    asm volatile("cp.async.ca.shared.global [%0], [%1], 16;" :: "r"(dst), "l"(src))
#define CP_COMMIT() asm volatile("cp.async.commit_group;")
#define CP_WAIT0() asm volatile("cp.async.wait_group 0;")

// ---------------- CSR build ----------------
__global__ void zero_cnt_kernel() {
    int i = blockIdx.x * blockDim.x + threadIdx.x;
    if (i < NBUCK) g_cnt[i] = 0;
}

__global__ void hist_kernel(const int* __restrict__ dst0, const int* __restrict__ dst1) {
    int e = blockIdx.x * blockDim.x + threadIdx.x;
    if (e >= N_EDGES) return;
    int rel = blockIdx.y;
    const int* dst = rel ? dst1 : dst0;
    atomicAdd(&g_cnt[rel * N_NODES + dst[e]], 1);
}

// blocks of 2048 elements (256 thr x 8); per-block exclusive prefix + block sums
__global__ void scan1_kernel() {
    __shared__ int sh[256];
    int b = blockIdx.x, t = threadIdx.x;
    int base = b * 2048 + t * 8;
    int v[8];
    int sum = 0;
#pragma unroll
    for (int j = 0; j < 8; j++) {
        int idx = base + j;
        v[j] = (idx < NBUCK) ? g_cnt[idx] : 0;
        sum += v[j];
    }
    sh[t] = sum;
    __syncthreads();
    for (int off = 1; off < 256; off <<= 1) {
        int y = (t >= off) ? sh[t - off] : 0;
        __syncthreads();
        sh[t] += y;
        __syncthreads();
    }
    if (t == 255) g_bsum[b] = sh[255];
    int run = sh[t] - sum;   // exclusive within block
#pragma unroll
    for (int j = 0; j < 8; j++) {
        int idx = base + j;
        if (idx < NBUCK) g_off[idx] = run;
        run += v[j];
    }
}

__global__ void scan2_kernel() {
    __shared__ int sh[256];
    int t = threadIdx.x;
    int v = (t < SCAN_NB) ? g_bsum[t] : 0;
    sh[t] = v;
    __syncthreads();
    for (int off = 1; off < 256; off <<= 1) {
        int y = (t >= off) ? sh[t - off] : 0;
        __syncthreads();
        sh[t] += y;
        __syncthreads();
    }
    g_boff[t] = sh[t] - v;   // exclusive block offset
}

__global__ void scan3_kernel() {
    int b = blockIdx.x, t = threadIdx.x;
    int add = g_boff[b];
    int base = b * 2048 + t * 8;
#pragma unroll
    for (int j = 0; j < 8; j++) {
        int idx = base + j;
        if (idx < NBUCK) {
            int o = g_off[idx] + add;
            g_off[idx] = o;
            g_head[idx] = o;
        }
    }
    if (b == 0 && t == 0) g_off[NBUCK] = 2 * N_EDGES;
}

__global__ void scatter_kernel(const int* __restrict__ src0, const int* __restrict__ dst0,
                               const int* __restrict__ src1, const int* __restrict__ dst1) {
    int e = blockIdx.x * blockDim.x + threadIdx.x;
    if (e >= N_EDGES) return;
    int rel = blockIdx.y;
    const int* src = rel ? src1 : src0;
    const int* dst = rel ? dst1 : dst0;
    int pos = atomicAdd(&g_head[rel * N_NODES + dst[e]], 1);
    g_esrc[pos] = src[e];
}

// ---------------- fold node-type + edge-type linears; emit fp16 transposed ----------------
__global__ void prep_kernel(const float* __restrict__ Wk, const float* __restrict__ bk,
                            const float* __restrict__ Wq, const float* __restrict__ bq,
                            const float* __restrict__ Wv, const float* __restrict__ bv,
                            const float* __restrict__ We0, const float* __restrict__ be0,
                            const float* __restrict__ We1, const float* __restrict__ be1) {
    int c = blockIdx.x;           // 0..767
    int i = threadIdx.x;          // 0..127  (k index)
    int r = c / 384;
    int rem = c % 384;
    int t = rem / 128;
    int j = rem % 128;
    const float* We = r ? We1 : We0;
    const float* be = r ? be1 : be0;
    const float* Wt = (t == 0) ? Wk : (t == 1) ? Wq : Wv;
    const float* bt = (t == 0) ? bk : (t == 1) ? bq : bv;
    const float scale = (t == 1) ? 0.125f : 1.0f;

    __shared__ float sWe[128];
    sWe[i] = We[i * 128 + j];
    __syncthreads();

    float acc = 0.f;
#pragma unroll 8
    for (int m = 0; m < 128; m++) acc += Wt[i * 128 + m] * sWe[m];
    g_WCt[c * 128 + i] = __float2half_rn(acc * scale);

    if (i == 0) {
        float b = 0.f;
        for (int m = 0; m < 128; m++) b += bt[m] * sWe[m];
        g_bc[c] = (b + be[j]) * scale;
    }
}

__global__ void prep_wo_kernel(const float* __restrict__ Wo) {
    int n = blockIdx.x;   // 0..127
    int i = threadIdx.x;  // 0..127 (k index)
    g_Wot[n * 128 + i] = __float2half_rn(Wo[i * 128 + n]);
}

// ---------------- HMMA GEMM ----------------
// MODE 1: C_kqv = fp16(A) @ Bt^T + bias, single pass, routed fp16 K/Q/V outputs.
// MODE 0: C = (upd0 + upd1) @ Bt^T + bias, fp16 2-pass big-little, fp32 C.
// CTA: 256 threads, 128 rows, warp tile 32x64. 2 CTAs/SM.
template <int MODE>
__global__ void __launch_bounds__(256, 2) hgemm_kernel(
    const float* __restrict__ A,
    const __half* __restrict__ Bt,
    const float* __restrict__ bias,
    float* __restrict__ C,
    int COLS, int Mrows, int NTILES) {
    extern __shared__ char smem[];
    const uint32_t sb = smem_u32(smem);
    const int tid = threadIdx.x;
    const int m0 = blockIdx.x * 128;
    const int SM_AL = 32768;
    const int SM_BH = (MODE == 0) ? 65536 : 32768;

    auto loadB = [&](int n0) {
#pragma unroll
        for (int it = 0; it < 8; it++) {
            int u = tid + it * 256;          // 0..2047
            int row = u >> 4, kb = u & 15;
            uint32_t off = row * 256 + ((uint32_t)(kb ^ (row & 7)) << 4);
            const char* gh = (const char*)(Bt + (size_t)(n0 + row) * 128) + kb * 16;
            CP_ASYNC16(sb + SM_BH + off, gh);
        }
        CP_COMMIT();
    };
    loadB(0);

    // A tile: 128 rows, swizzled
#pragma unroll
    for (int it = 0; it < 8; it++) {
        int u = tid + it * 256;              // 0..2047
        int row = u >> 4, kb = u & 15;
        int gr = m0 + row;
        float4 v0 = make_float4(0.f, 0.f, 0.f, 0.f), v1 = v0;
        if (gr < Mrows) {
            if (MODE == 1) {
                const float* p = A + (size_t)gr * 128 + kb * 8;
                v0 = *(const float4*)p;
                v1 = *(const float4*)(p + 4);
            } else {
                const float* p0 = g_upd0 + (size_t)gr * 128 + kb * 8;
                const float* p1 = g_upd1 + (size_t)gr * 128 + kb * 8;
                float4 a0 = *(const float4*)p0, a1 = *(const float4*)(p0 + 4);
                float4 b0 = *(const float4*)p1, b1 = *(const float4*)(p1 + 4);
                v0 = make_float4(a0.x + b0.x, a0.y + b0.y, a0.z + b0.z, a0.w + b0.w);
                v1 = make_float4(a1.x + b1.x, a1.y + b1.y, a1.z + b1.z, a1.w + b1.w);
            }
        }
        uint32_t off = row * 256 + ((uint32_t)(kb ^ (row & 7)) << 4);
        if (MODE == 1) {
            uint32_t h0 = packh2(__float2half_rn(v0.x), __float2half_rn(v0.y));
            uint32_t h1 = packh2(__float2half_rn(v0.z), __float2half_rn(v0.w));
            uint32_t h2 = packh2(__float2half_rn(v1.x), __float2half_rn(v1.y));
            uint32_t h3 = packh2(__float2half_rn(v1.z), __float2half_rn(v1.w));
            *(uint4*)(smem + off) = make_uint4(h0, h1, h2, h3);
        } else {
            uint32_t h[4], l[4];
            split2h(v0.x, v0.y, h[0], l[0]);
            split2h(v0.z, v0.w, h[1], l[1]);
            split2h(v1.x, v1.y, h[2], l[2]);
            split2h(v1.z, v1.w, h[3], l[3]);
            *(uint4*)(smem + off) = make_uint4(h[0], h[1], h[2], h[3]);
            *(uint4*)(smem + SM_AL + off) = make_uint4(l[0], l[1], l[2], l[3]);
        }
    }

    // 8 warps -> 4m x 2n grid of 32m x 64n warp tiles
    const int wid = tid >> 5, lane = tid & 31;
    const int wm = wid & 3, wn = wid >> 2;
    const uint32_t x7 = lane & 7;
    const uint32_t aRow = wm * 32 + (lane & 15);
    const uint32_t akoff = lane >> 4;
    const uint32_t bRow = wn * 64 + (lane & 7) + ((lane >> 4) << 3);
    const uint32_t bkoff = (lane >> 3) & 1;
    const uint32_t ah_base = sb + aRow * 256;
    const uint32_t al_base = sb + SM_AL + aRow * 256;
    const uint32_t bh_base = sb + SM_BH + bRow * 256;
    const int g = lane >> 2, tg = lane & 3;

    for (int nt = 0; nt < NTILES; nt++) {
        CP_WAIT0();
        __syncthreads();

        float acc[2][8][4] = {};
#pragma unroll
        for (int kc = 0; kc < 8; kc++) {
            const uint32_t kxa = (((2 * kc + akoff) ^ x7) << 4);
            const uint32_t kxb = (((2 * kc + bkoff) ^ x7) << 4);
            uint32_t AH[2][4], BH[4][4];
#pragma unroll
            for (int ma = 0; ma < 2; ma++) LDSM4(AH[ma], ah_base + ma * 4096 + kxa);
#pragma unroll
            for (int nb = 0; nb < 4; nb++) LDSM4(BH[nb], bh_base + nb * 4096 + kxb);
#pragma unroll
            for (int ma = 0; ma < 2; ma++)
#pragma unroll
                for (int nb = 0; nb < 4; nb++) {
                    MMAH(acc[ma][nb * 2 + 0], AH[ma], BH[nb][0], BH[nb][1]);
                    MMAH(acc[ma][nb * 2 + 1], AH[ma], BH[nb][2], BH[nb][3]);
                }
            if (MODE == 0) {
                uint32_t AL[2][4];
#pragma unroll
                for (int ma = 0; ma < 2; ma++) LDSM4(AL[ma], al_base + ma * 4096 + kxa);
#pragma unroll
                for (int ma = 0; ma < 2; ma++)
#pragma unroll
                    for (int nb = 0; nb < 4; nb++) {
                        MMAH(acc[ma][nb * 2 + 0], AL[ma], BH[nb][0], BH[nb][1]);
                        MMAH(acc[ma][nb * 2 + 1], AL[ma], BH[nb][2], BH[nb][3]);
                    }
            }
        }

        __syncthreads();
        if (nt + 1 < NTILES) loadB((nt + 1) * 128);

        // ---- epilogue ----
        if (MODE == 0) {
#pragma unroll
            for (int ma = 0; ma < 2; ma++) {
                int row = m0 + wm * 32 + ma * 16 + g;
#pragma unroll
                for (int x = 0; x < 8; x++) {
                    int col = nt * 128 + wn * 64 + x * 8 + tg * 2;
                    float2 bb = *(const float2*)(bias + col);
                    float* c = acc[ma][x];
                    if (row < Mrows)
                        *(float2*)(C + (size_t)row * COLS + col) =
                            make_float2(c[0] + bb.x, c[1] + bb.y);
                    if (row + 8 < Mrows)
                        *(float2*)(C + (size_t)(row + 8) * COLS + col) =
                            make_float2(c[2] + bb.x, c[3] + bb.y);
                }
            }
        } else {
            int r = nt / 3, t = nt - r * 3;
            __half* hout = (t == 0 ? g_K : t == 1 ? g_Q : g_V) + (size_t)r * N_NODES * 128;
#pragma unroll
            for (int ma = 0; ma < 2; ma++) {
                int row = m0 + wm * 32 + ma * 16 + g;
#pragma unroll
                for (int x = 0; x < 8; x++) {
                    int j = wn * 64 + x * 8 + tg * 2;
                    float2 bb = *(const float2*)(bias + nt * 128 + j);
                    float* c = acc[ma][x];
                    if (row < Mrows)
                        *(__half2*)(hout + (size_t)row * 128 + j) =
                            __float22half2_rn(make_float2(c[0] + bb.x, c[1] + bb.y));
                    if (row + 8 < Mrows)
                        *(__half2*)(hout + (size_t)(row + 8) * 128 + j) =
                            __float22half2_rn(make_float2(c[2] + bb.x, c[3] + bb.y));
                }
            }
        }
    }
}

// ---------------- gather: warp per (node, rel); softmax-normalized message sum ----------------
__global__ void __launch_bounds__(256) gather_kernel() {
    int wid = threadIdx.x >> 5, lane = threadIdx.x & 31;
    int node = blockIdx.x * 8 + wid;
    if (node >= N_NODES) return;
    int rel = blockIdx.y;
    int bucket = rel * N_NODES + node;
    int o0 = g_off[bucket], o1 = g_off[bucket + 1];
    float* outp = (rel ? g_upd1 : g_upd0) + (size_t)node * 128 + lane * 4;
    if (o0 == o1) {
        *(float4*)outp = make_float4(0.f, 0.f, 0.f, 0.f);
        return;
    }
    const size_t rbase = (size_t)rel * N_NODES * 128;
    float2 qraw = ((const float2*)(g_Q + rbase + (size_t)node * 128))[lane];
    __half2 q0 = *reinterpret_cast<__half2*>(&qraw.x);
    __half2 q1 = *reinterpret_cast<__half2*>(&qraw.y);
    float2 fq0 = __half22float2(q0), fq1 = __half22float2(q1);

    float s = 0.f;
    float4 acc = make_float4(0.f, 0.f, 0.f, 0.f);
    for (int i = o0; i < o1; i++) {
        int sn = g_esrc[i];
        float2 kraw = ((const float2*)(g_K + rbase + (size_t)sn * 128))[lane];
        __half2 a0 = *reinterpret_cast<__half2*>(&kraw.x);
        __half2 a1 = *reinterpret_cast<__half2*>(&kraw.y);
        float2 fa0 = __half22float2(a0), fa1 = __half22float2(a1);
        float p = fa0.x * fq0.x + fa0.y * fq0.y + fa1.x * fq1.x + fa1.y * fq1.y;
        // reduce within 16-lane halves (head0: lanes 0-15, head1: 16-31)
        p += __shfl_xor_sync(0xffffffffu, p, 1);
        p += __shfl_xor_sync(0xffffffffu, p, 2);
        p += __shfl_xor_sync(0xffffffffu, p, 4);
        p += __shfl_xor_sync(0xffffffffu, p, 8);
        float el = expf(p);
        s += el;
        float2 vraw = ((const float2*)(g_V + rbase + (size_t)sn * 128))[lane];
        __half2 v0 = *reinterpret_cast<__half2*>(&vraw.x);
        __half2 v1 = *reinterpret_cast<__half2*>(&vraw.y);
        float2 f0 = __half22float2(v0), f1 = __half22float2(v1);
        acc.x += f0.x * el;
        acc.y += f0.y * el;
        acc.z += f1.x * el;
        acc.w += f1.y * el;
    }
    float inv = 1.f / s;
    *(float4*)outp = make_float4(acc.x * inv, acc.y * inv, acc.z * inv, acc.w * inv);
}

// ---------------- launch ----------------
extern "C" void kernel_launch(void* const* d_in, const int* in_sizes, int n_in,
                              void* d_out, int out_size) {
    const float* feat = (const float*)d_in[0];
    const int* src0 = (const int*)d_in[1];
    const int* dst0 = (const int*)d_in[2];
    const int* src1 = (const int*)d_in[3];
    const int* dst1 = (const int*)d_in[4];
    const float* Wk = (const float*)d_in[5];
    const float* bk = (const float*)d_in[6];
    const float* Wq = (const float*)d_in[7];
    const float* bq = (const float*)d_in[8];
    const float* Wv = (const float*)d_in[9];
    const float* bv = (const float*)d_in[10];
    const float* Wo = (const float*)d_in[11];
    const float* bo = (const float*)d_in[12];
    const float* We0 = (const float*)d_in[13];
    const float* be0 = (const float*)d_in[14];
    const float* We1 = (const float*)d_in[15];
    const float* be1 = (const float*)d_in[16];
    float* out = (float*)d_out;

    void *pbc, *pWC, *pWo, *pU0;
    cudaGetSymbolAddress(&pbc, g_bc);
    cudaGetSymbolAddress(&pWC, g_WCt);
    cudaGetSymbolAddress(&pWo, g_Wot);
    cudaGetSymbolAddress(&pU0, g_upd0);

    cudaFuncSetAttribute(hgemm_kernel<1>, cudaFuncAttributeMaxDynamicSharedMemorySize, 65536);
    cudaFuncSetAttribute(hgemm_kernel<0>, cudaFuncAttributeMaxDynamicSharedMemorySize, 98304);

    // CSR build
    zero_cnt_kernel<<<(NBUCK + 255) / 256, 256>>>();
    hist_kernel<<<dim3((N_EDGES + 255) / 256, 2), 256>>>(dst0, dst1);
    scan1_kernel<<<SCAN_NB, 256>>>();
    scan2_kernel<<<1, 256>>>();
    scan3_kernel<<<SCAN_NB, 256>>>();
    scatter_kernel<<<dim3((N_EDGES + 255) / 256, 2), 256>>>(src0, dst0, src1, dst1);

    // weights
    prep_kernel<<<KQV_COLS, 128>>>(Wk, bk, Wq, bq, Wv, bv, We0, be0, We1, be1);
    prep_wo_kernel<<<128, 128>>>(Wo);

    const int Mtiles = (N_NODES + 127) / 128;  // 1563

    // K/Q/V = feat @ WC + bc   (single-pass fp16)
    hgemm_kernel<1><<<Mtiles, 256, 65536>>>(
        feat, (const __half*)pWC, (const float*)pbc, nullptr, KQV_COLS, N_NODES, 6);

    // per-destination softmax + message aggregation
    gather_kernel<<<dim3((N_NODES + 7) / 8, 2), 256>>>();

    // out = (upd0 + upd1) @ Wo + bo   (2-pass fp16)
    hgemm_kernel<0><<<Mtiles, 256, 98304>>>(
        (const float*)pU0, (const __half*)pWo, bo, out, DIM, N_NODES, 1);
}